// round 13
// baseline (speedup 1.0000x reference)
#include <cuda_runtime.h>
#include <cuda_bf16.h>
#include <cstdint>

#define NN 100000
#define EE 1600000
#define HH 128
#define GG 500

// ---------------- scratch (static __device__ globals; no allocation) ----------------
__device__ float g_bufA[NN * HH];     // ping
__device__ float g_bufB[NN * HH];     // pong (xw)
__device__ float g_deg[NN];           // deg -> dinv (in place)
__device__ int   g_cnt[NN];           // histogram / fill counter
__device__ int   g_rowptr[NN + 1];
__device__ int2  g_epack[EE];         // {row, norm-bits} per CSR-ordered edge
__device__ int   g_part[128];         // scan partials (98 used)
__device__ int   g_aIsBatch;          // input-disambiguation flag
__device__ float g_wfhi[3 * 16896];   // W hi tf32, fragment-ready 132-stride, per layer
__device__ float g_wflo[3 * 16896];   // W lo tf32

__device__ __forceinline__ void tf32_split(float x, uint32_t& hi, uint32_t& lo) {
    asm("cvt.rna.tf32.f32 %0, %1;" : "=r"(hi) : "f"(x));
    float r = x - __uint_as_float(hi);
    asm("cvt.rna.tf32.f32 %0, %1;" : "=r"(lo) : "f"(r));
}

// ---------------- z/batch detector + one-shot W split (fused: 1 launch) ----------------
// block 0: detect. blocks 1..96: split 3 conv weights into fragment-ready gmem:
//   WF[layer*16896 + k*132 + (n&7)*16 + (n>>3)] = split(W[k][n])
__global__ void k_detect(const int* __restrict__ a,
                         const float* __restrict__ w0, const float* __restrict__ w1,
                         const float* __restrict__ w2) {
    if (blockIdx.x == 0) {
        int i = threadIdx.x;                       // 512 threads
        int v  = a[i];
        int vp = (i > 0) ? a[i - 1] : 0;
        int ok = (v >= 0) && (v < GG) && (v >= vp);
        int all = __syncthreads_and(ok);
        if (i == 0) g_aIsBatch = all;
    } else {
        int idx = (blockIdx.x - 1) * 512 + threadIdx.x;   // 0..49151
        int layer = idx >> 14;
        int e = idx & 16383;
        int k = e >> 7, n = e & 127;
        const float* Wsel = (layer == 0) ? w0 : ((layer == 1) ? w1 : w2);
        uint32_t h, l;
        tf32_split(Wsel[k * 128 + n], h, l);
        int off = layer * 16896 + k * 132 + (n & 7) * 16 + (n >> 3);
        g_wfhi[off] = __uint_as_float(h);
        g_wflo[off] = __uint_as_float(l);
    }
}

// ---------------- degree ----------------
__global__ void k_init() {
    int i = blockIdx.x * blockDim.x + threadIdx.x;
    if (i < NN) { g_deg[i] = 1.0f; g_cnt[i] = 0; }   // self-loop weight 1
}

__global__ void k_count(const int* __restrict__ ei, const float* __restrict__ w) {
    int e = blockIdx.x * blockDim.x + threadIdx.x;
    if (e < EE) {
        int c = ei[EE + e];
        atomicAdd(&g_deg[c], w[e]);
        atomicAdd(&g_cnt[c], 1);
    }
}

// ---------------- CSR build (scan1 also computes dinv in place) ----------------
__global__ void k_scan1() {   // blocks of 1024 over g_cnt
    __shared__ int s[1024];
    int tid = threadIdx.x;
    int i = blockIdx.x * 1024 + tid;
    if (i < NN) { float d = g_deg[i]; g_deg[i] = (d > 0.f) ? rsqrtf(d) : 0.f; }
    int v = (i < NN) ? g_cnt[i] : 0;
    s[tid] = v; __syncthreads();
    #pragma unroll
    for (int off = 1; off < 1024; off <<= 1) {
        int t = (tid >= off) ? s[tid - off] : 0;
        __syncthreads();
        s[tid] += t; __syncthreads();
    }
    if (i < NN) g_rowptr[i] = s[tid] - v;         // exclusive within block
    if (tid == 1023) g_part[blockIdx.x] = s[1023];
}

__global__ void k_scan2(int nblocks) {   // one 128-thread block, parallel scan
    __shared__ int s[128];
    int tid = threadIdx.x;
    int v = (tid < nblocks) ? g_part[tid] : 0;
    s[tid] = v; __syncthreads();
    #pragma unroll
    for (int off = 1; off < 128; off <<= 1) {
        int t = (tid >= off) ? s[tid - off] : 0;
        __syncthreads();
        s[tid] += t; __syncthreads();
    }
    if (tid < nblocks) g_part[tid] = s[tid] - v;  // exclusive
    if (tid == 127) g_rowptr[NN] = s[127];
}

__global__ void k_scan3() {
    int i = blockIdx.x * blockDim.x + threadIdx.x;
    if (i < NN) { g_rowptr[i] += g_part[i >> 10]; g_cnt[i] = 0; }
}

// fused: CSR fill + norm computation + epack write (one edge pass)
__global__ void k_fill(const int* __restrict__ ei, const float* __restrict__ w) {
    int e = blockIdx.x * blockDim.x + threadIdx.x;
    if (e < EE) {
        int r = ei[e];
        int c = ei[EE + e];
        float nm = g_deg[r] * w[e] * g_deg[c];    // g_deg holds dinv
        int pos = g_rowptr[c] + atomicAdd(&g_cnt[c], 1);
        g_epack[pos] = make_int2(r, __float_as_int(nm));
    }
}

// ---------------- 3xTF32 tensor-core GEMM: Y[M,128] = X[M,128] @ W[128,128] ----------------
// BM=128, 512 threads (16 warps). Warp tile m32 x n32: 2 m16-tiles x 4 n8-tiles.
// Wavefront budget: 8 (X) + 16 (W frag LDS.128) = 24 wf per 24 MMAs per warp per k-step
// (1.5x less LDS than R9/R12 configs at equal warp count).
#define MMA_TF32(acc, a0, a1, a2, a3, b0, b1)                               \
    asm volatile(                                                           \
        "mma.sync.aligned.m16n8k8.row.col.f32.tf32.tf32.f32 "               \
        "{%0,%1,%2,%3},{%4,%5,%6,%7},{%8,%9},{%0,%1,%2,%3};\n"              \
        : "+f"(acc[0]), "+f"(acc[1]), "+f"(acc[2]), "+f"(acc[3])            \
        : "r"(a0), "r"(a1), "r"(a2), "r"(a3), "r"(b0), "r"(b1))

__global__ void __launch_bounds__(512, 1)
k_gemm(const float* __restrict__ X, int layer, float* __restrict__ Y,
       const int* __restrict__ za, const int* __restrict__ zb,
       const float* __restrict__ ztab, int useEmbed) {
    extern __shared__ float sm[];
    float* Xs   = sm;                     // [128][132] = 16896 floats
    float* WFhi = sm + 16896;             // fragment-ready, 132-stride
    float* WFlo = WFhi + 16896;
    int tid = threadIdx.x;
    int row0 = blockIdx.x * 128;

    // prologue: straight float4 copy of pre-split W (4224 float4 each)
    {
        const float4* shi = (const float4*)(g_wfhi + layer * 16896);
        const float4* slo = (const float4*)(g_wflo + layer * 16896);
        float4* dhi = (float4*)WFhi;
        float4* dlo = (float4*)WFlo;
        for (int idx = tid; idx < 4224; idx += 512) {
            dhi[idx] = shi[idx];
            dlo[idx] = slo[idx];
        }
    }
    // load X tile (raw fp32); layer 0: X row = ztab[z[row]]
    const int* zsel = g_aIsBatch ? zb : za;
    #pragma unroll
    for (int i = 0; i < 8; ++i) {
        int idx = tid + i * 512;
        int m = idx >> 5, kv = idx & 31;
        int r = row0 + m;
        float4 v = make_float4(0.f, 0.f, 0.f, 0.f);
        if (r < NN) {
            const float4* src = useEmbed ? ((const float4*)ztab + (size_t)zsel[r] * 32)
                                         : ((const float4*)X + (size_t)r * 32);
            v = src[kv];
        }
        *(float4*)&Xs[m * 132 + kv * 4] = v;
    }
    __syncthreads();

    int wid = tid >> 5, lane = tid & 31;
    int m0 = (wid & 3) * 32;          // 4 m32 groups -> 128 rows
    int ng = wid >> 2;                // 0..3
    int n0 = ng * 32;                 // n32 per warp
    int g  = lane >> 2;               // 0..7
    int q  = lane & 3;                // 0..3

    float acc[2][4][4];
    #pragma unroll
    for (int mt = 0; mt < 2; ++mt)
        #pragma unroll
        for (int nt = 0; nt < 4; ++nt)
            #pragma unroll
            for (int j = 0; j < 4; ++j) acc[mt][nt][j] = 0.f;

    int xb00 = (m0 + g) * 132 + q;          // mt=0 rows g, g+8
    int xb01 = (m0 + 8 + g) * 132 + q;
    int xb10 = (m0 + 16 + g) * 132 + q;     // mt=1 rows 16+g, 24+g
    int xb11 = (m0 + 24 + g) * 132 + q;
    int wbase = q * 132 + g * 16 + ng * 4;  // + kb*132 per step; +4*132 for k-hi half

    #pragma unroll 2
    for (int ks = 0; ks < 16; ++ks) {
        int kb = ks * 8;
        uint32_t ah[2][4], al[2][4];
        tf32_split(Xs[xb00 + kb],     ah[0][0], al[0][0]);
        tf32_split(Xs[xb01 + kb],     ah[0][1], al[0][1]);
        tf32_split(Xs[xb00 + kb + 4], ah[0][2], al[0][2]);
        tf32_split(Xs[xb01 + kb + 4], ah[0][3], al[0][3]);
        tf32_split(Xs[xb10 + kb],     ah[1][0], al[1][0]);
        tf32_split(Xs[xb11 + kb],     ah[1][1], al[1][1]);
        tf32_split(Xs[xb10 + kb + 4], ah[1][2], al[1][2]);
        tf32_split(Xs[xb11 + kb + 4], ah[1][3], al[1][3]);

        int wb = wbase + kb * 132;
        float4 blA = *(float4*)&WFlo[wb];             // k = kb+q,   nt 0..3
        float4 blB = *(float4*)&WFlo[wb + 4 * 132];   // k = kb+q+4
        float4 bhA = *(float4*)&WFhi[wb];
        float4 bhB = *(float4*)&WFhi[wb + 4 * 132];
        uint32_t bl0[4] = {__float_as_uint(blA.x), __float_as_uint(blA.y),
                           __float_as_uint(blA.z), __float_as_uint(blA.w)};
        uint32_t bl1[4] = {__float_as_uint(blB.x), __float_as_uint(blB.y),
                           __float_as_uint(blB.z), __float_as_uint(blB.w)};
        uint32_t bh0[4] = {__float_as_uint(bhA.x), __float_as_uint(bhA.y),
                           __float_as_uint(bhA.z), __float_as_uint(bhA.w)};
        uint32_t bh1[4] = {__float_as_uint(bhB.x), __float_as_uint(bhB.y),
                           __float_as_uint(bhB.z), __float_as_uint(bhB.w)};

        #pragma unroll
        for (int mt = 0; mt < 2; ++mt) {
            #pragma unroll
            for (int nt = 0; nt < 4; ++nt) {
                MMA_TF32(acc[mt][nt], ah[mt][0], ah[mt][1], ah[mt][2], ah[mt][3],
                         bl0[nt], bl1[nt]);
                MMA_TF32(acc[mt][nt], al[mt][0], al[mt][1], al[mt][2], al[mt][3],
                         bh0[nt], bh1[nt]);
                MMA_TF32(acc[mt][nt], ah[mt][0], ah[mt][1], ah[mt][2], ah[mt][3],
                         bh0[nt], bh1[nt]);
            }
        }
    }

    // store: c0,c1 -> (row, 2q),(row, 2q+1); c2,c3 -> row+8
    #pragma unroll
    for (int mt = 0; mt < 2; ++mt) {
        int r = row0 + m0 + mt * 16 + g;
        #pragma unroll
        for (int nt = 0; nt < 4; ++nt) {
            int cc = n0 + nt * 8 + 2 * q;
            if (r < NN)
                *(float2*)&Y[r * 128 + cc] = make_float2(acc[mt][nt][0], acc[mt][nt][1]);
            if (r + 8 < NN)
                *(float2*)&Y[(r + 8) * 128 + cc] = make_float2(acc[mt][nt][2], acc[mt][nt][3]);
        }
    }
}

// ---------------- CSR gather-aggregate + bias (+ReLU) fused ----------------
// one warp per node, one float4 per lane; 2-deep rotating software pipeline
__global__ void k_gather(const float* __restrict__ xw, const float* __restrict__ bias,
                         float* __restrict__ out, int do_relu) {
    int gtid = blockIdx.x * blockDim.x + threadIdx.x;
    int v = gtid >> 5;
    int lane = gtid & 31;
    if (v >= NN) return;

    const float4* xwv = (const float4*)xw;
    float di = g_deg[v];                 // holds dinv
    float s = di * di;                   // self-loop norm
    float4 acc = xwv[(size_t)v * 32 + lane];
    acc.x *= s; acc.y *= s; acc.z *= s; acc.w *= s;

    int p = g_rowptr[v], end = g_rowptr[v + 1];
    if (p < end) {
        int2 pr = g_epack[p];
        for (++p; p < end; ++p) {
            int2 nxt = g_epack[p];
            float nm = __int_as_float(pr.y);
            float4 xv = xwv[(size_t)pr.x * 32 + lane];
            acc.x += nm * xv.x; acc.y += nm * xv.y;
            acc.z += nm * xv.z; acc.w += nm * xv.w;
            pr = nxt;
        }
        float nm = __int_as_float(pr.y);
        float4 xv = xwv[(size_t)pr.x * 32 + lane];
        acc.x += nm * xv.x; acc.y += nm * xv.y;
        acc.z += nm * xv.z; acc.w += nm * xv.w;
    }

    float4 b = ((const float4*)bias)[lane];
    acc.x += b.x; acc.y += b.y; acc.z += b.z; acc.w += b.w;
    if (do_relu) {
        acc.x = fmaxf(acc.x, 0.f); acc.y = fmaxf(acc.y, 0.f);
        acc.z = fmaxf(acc.z, 0.f); acc.w = fmaxf(acc.w, 0.f);
    }
    ((float4*)out)[(size_t)v * 32 + lane] = acc;
}

// ---------------- readout ----------------
__global__ void k_readout(const float* __restrict__ X,
                          const int* __restrict__ cand_a, const int* __restrict__ cand_b,
                          const float* __restrict__ W1, const float* __restrict__ b1,
                          const float* __restrict__ W2, const float* __restrict__ b2,
                          float* __restrict__ out) {
    const int* batch = g_aIsBatch ? cand_a : cand_b;
    __shared__ float h[128];
    __shared__ int sc;
    __shared__ float red[4];
    int g = blockIdx.x, j = threadIdx.x;
    if (j == 0) {   // searchsorted: first idx with batch[idx] >= g
        int lo = 0, hi = NN;
        while (lo < hi) { int mid = (lo + hi) >> 1; if (batch[mid] < g) lo = mid + 1; else hi = mid; }
        sc = lo;
    }
    __syncthreads();
    int c = sc;
    h[j] = X[c * 128 + j] * X[(c + 1) * 128 + j];
    __syncthreads();
    float acc = b1[j];
    #pragma unroll 8
    for (int k = 0; k < 128; ++k) acc += h[k] * W1[k * 128 + j];
    acc = fmaxf(acc, 0.f);
    float v = acc * W2[j];
    #pragma unroll
    for (int o = 16; o; o >>= 1) v += __shfl_xor_sync(0xffffffffu, v, o);
    if ((j & 31) == 0) red[j >> 5] = v;
    __syncthreads();
    if (j == 0) out[g] = red[0] + red[1] + red[2] + red[3] + b2[0];
}

// ---------------- launch: bind inputs BY SIZE (metadata order is unknown) ----------------
extern "C" void kernel_launch(void* const* d_in, const int* in_sizes, int n_in,
                              void* d_out, int out_size) {
    const int* i100k[2] = {0, 0}; int n100k = 0;
    const void* v16k[4] = {0, 0, 0, 0}; int n16k = 0;
    const void* v128[8] = {0, 0, 0, 0, 0, 0, 0, 0}; int n128 = 0;
    const int*   ei = 0; const float* ew = 0; const float* ztab = 0;
    const float* packedW = 0; const float* packedB = 0; const float* lin2b = 0;

    for (int i = 0; i < n_in; ++i) {
        int s = in_sizes[i];
        if      (s == 2 * EE)      ei   = (const int*)d_in[i];
        else if (s == EE)          ew   = (const float*)d_in[i];
        else if (s == 1000 * HH)   ztab = (const float*)d_in[i];
        else if (s == NN)          { if (n100k < 2) i100k[n100k++] = (const int*)d_in[i]; }
        else if (s == HH * HH)     { if (n16k < 4) v16k[n16k++] = d_in[i]; }
        else if (s == 3 * HH * HH) packedW = (const float*)d_in[i];
        else if (s == HH)          { if (n128 < 8) v128[n128++] = d_in[i]; }
        else if (s == 3 * HH)      packedB = (const float*)d_in[i];
        else if (s == 1)           lin2b = (const float*)d_in[i];
    }

    const float* convW[3]; const float* convB[3];
    const float* lin1W; const float* lin1b; const float* lin2W;
    if (packedW) {
        convW[0] = packedW; convW[1] = packedW + HH * HH; convW[2] = packedW + 2 * HH * HH;
        lin1W = (const float*)v16k[0];
    } else {
        convW[0] = (const float*)v16k[0]; convW[1] = (const float*)v16k[1];
        convW[2] = (const float*)v16k[2]; lin1W = (const float*)v16k[3];
    }
    if (packedB) {
        convB[0] = packedB; convB[1] = packedB + HH; convB[2] = packedB + 2 * HH;
        lin1b = (const float*)v128[0]; lin2W = (const float*)v128[1];
    } else {
        convB[0] = (const float*)v128[0]; convB[1] = (const float*)v128[1];
        convB[2] = (const float*)v128[2];
        lin1b = (const float*)v128[3]; lin2W = (const float*)v128[4];
    }
    float* out = (float*)d_out;

    float *A, *B;
    cudaGetSymbolAddress((void**)&A, g_bufA);
    cudaGetSymbolAddress((void**)&B, g_bufB);

    const int SMEM = 3 * 16896 * 4;  // 202752: Xs + WFhi + WFlo
    cudaFuncSetAttribute(k_gemm, cudaFuncAttributeMaxDynamicSharedMemorySize, SMEM);

    const int TB = 256;
    int nblk_n  = (NN + TB - 1) / TB;         // 391
    int nblk_e  = (EE + TB - 1) / TB;         // 6250
    int nblk_nh = (NN * 32 + TB - 1) / TB;    // 12500
    int scan_blocks = (NN + 1023) / 1024;     // 98
    int gemm_blocks = (NN + 127) / 128;       // 782

    // launches 0..2 (detect fused with one-shot W split into fragment layout)
    k_detect<<<97, 512>>>(i100k[0], convW[0], convW[1], convW[2]);
    k_init <<<nblk_n, TB>>>();
    k_count<<<nblk_e, TB>>>(ei, ew);

    // launch 3: layer-0 GEMM (embedding fused; independent of CSR) — stays in the
    // profiler's capture window.
    k_gemm<<<gemm_blocks, 512, SMEM>>>(A, 0, B, i100k[0], i100k[1], ztab, 1);

    // CSR build
    k_scan1<<<scan_blocks, 1024>>>();         // also computes dinv
    k_scan2<<<1, 128>>>(scan_blocks);
    k_scan3<<<nblk_n, TB>>>();
    k_fill <<<nblk_e, TB>>>(ei, ew);

    // layer 0 aggregate, then layers 1,2
    k_gather<<<nblk_nh, TB>>>(B, convB[0], A, 1);
    for (int l = 1; l < 3; ++l) {
        k_gemm  <<<gemm_blocks, 512, SMEM>>>(A, l, B, i100k[0], i100k[1], ztab, 0);
        k_gather<<<nblk_nh, TB>>>(B, convB[l], A, (l < 2) ? 1 : 0);
    }

    // readout
    k_readout<<<GG, 128>>>(A, i100k[0], i100k[1], lin1W, lin1b, lin2W, lin2b, out);
}

// round 14
// speedup vs baseline: 1.0035x; 1.0035x over previous
#include <cuda_runtime.h>
#include <cuda_bf16.h>
#include <cstdint>

#define NN 100000
#define EE 1600000
#define HH 128
#define GG 500

// ---------------- scratch (static __device__ globals; no allocation) ----------------
__device__ float g_bufA[NN * HH];     // ping
__device__ float g_bufB[NN * HH];     // pong (xw)
__device__ float g_deg[NN];           // deg -> dinv (in place)
__device__ int   g_cnt[NN];           // histogram / fill counter
__device__ int   g_rowptr[NN + 1];
__device__ int2  g_epack[EE];         // {row, norm-bits} per CSR-ordered edge
__device__ int   g_part[128];         // scan partials (98 used)
__device__ int   g_aIsBatch;          // input-disambiguation flag
__device__ float g_wfhi[3 * 16896];   // W hi tf32, fragment-ready 132-stride, per layer
__device__ float g_wflo[3 * 16896];   // W lo tf32

__device__ __forceinline__ void tf32_split(float x, uint32_t& hi, uint32_t& lo) {
    asm("cvt.rna.tf32.f32 %0, %1;" : "=r"(hi) : "f"(x));
    float r = x - __uint_as_float(hi);
    asm("cvt.rna.tf32.f32 %0, %1;" : "=r"(lo) : "f"(r));
}

// ---------------- detector + one-shot W split + deg init (fused: 1 launch) ----------------
// block 0: z/batch detect. blocks 1..96: split conv weights into fragment-ready gmem:
//   WF[layer*16896 + k*132 + (n&7)*16 + (n>>3)] = split(W[k][n])
// blocks 97..292: init g_deg/g_cnt.
__global__ void k_detect(const int* __restrict__ a,
                         const float* __restrict__ w0, const float* __restrict__ w1,
                         const float* __restrict__ w2) {
    if (blockIdx.x == 0) {
        int i = threadIdx.x;                       // 512 threads
        int v  = a[i];
        int vp = (i > 0) ? a[i - 1] : 0;
        int ok = (v >= 0) && (v < GG) && (v >= vp);
        int all = __syncthreads_and(ok);
        if (i == 0) g_aIsBatch = all;
    } else if (blockIdx.x <= 96) {
        int idx = (blockIdx.x - 1) * 512 + threadIdx.x;   // 0..49151
        int layer = idx >> 14;
        int e = idx & 16383;
        int k = e >> 7, n = e & 127;
        const float* Wsel = (layer == 0) ? w0 : ((layer == 1) ? w1 : w2);
        uint32_t h, l;
        tf32_split(Wsel[k * 128 + n], h, l);
        int off = layer * 16896 + k * 132 + (n & 7) * 16 + (n >> 3);
        g_wfhi[off] = __uint_as_float(h);
        g_wflo[off] = __uint_as_float(l);
    } else {
        int i = (int)(blockIdx.x - 97) * 512 + threadIdx.x;
        if (i < NN) { g_deg[i] = 1.0f; g_cnt[i] = 0; }   // self-loop weight 1
    }
}

__global__ void k_count(const int* __restrict__ ei, const float* __restrict__ w) {
    int e = blockIdx.x * blockDim.x + threadIdx.x;
    if (e < EE) {
        int c = ei[EE + e];
        atomicAdd(&g_deg[c], w[e]);
        atomicAdd(&g_cnt[c], 1);
    }
}

// ---------------- CSR build (scan1 also computes dinv in place) ----------------
__global__ void k_scan1() {   // blocks of 1024 over g_cnt
    __shared__ int s[1024];
    int tid = threadIdx.x;
    int i = blockIdx.x * 1024 + tid;
    if (i < NN) { float d = g_deg[i]; g_deg[i] = (d > 0.f) ? rsqrtf(d) : 0.f; }
    int v = (i < NN) ? g_cnt[i] : 0;
    s[tid] = v; __syncthreads();
    #pragma unroll
    for (int off = 1; off < 1024; off <<= 1) {
        int t = (tid >= off) ? s[tid - off] : 0;
        __syncthreads();
        s[tid] += t; __syncthreads();
    }
    if (i < NN) g_rowptr[i] = s[tid] - v;         // exclusive within block
    if (tid == 1023) g_part[blockIdx.x] = s[1023];
}

__global__ void k_scan2(int nblocks) {   // one 128-thread block, parallel scan
    __shared__ int s[128];
    int tid = threadIdx.x;
    int v = (tid < nblocks) ? g_part[tid] : 0;
    s[tid] = v; __syncthreads();
    #pragma unroll
    for (int off = 1; off < 128; off <<= 1) {
        int t = (tid >= off) ? s[tid - off] : 0;
        __syncthreads();
        s[tid] += t; __syncthreads();
    }
    if (tid < nblocks) g_part[tid] = s[tid] - v;  // exclusive
    if (tid == 127) g_rowptr[NN] = s[127];
}

__global__ void k_scan3() {
    int i = blockIdx.x * blockDim.x + threadIdx.x;
    if (i < NN) { g_rowptr[i] += g_part[i >> 10]; g_cnt[i] = 0; }
}

// fused: CSR fill + norm computation + epack write (one edge pass)
__global__ void k_fill(const int* __restrict__ ei, const float* __restrict__ w) {
    int e = blockIdx.x * blockDim.x + threadIdx.x;
    if (e < EE) {
        int r = ei[e];
        int c = ei[EE + e];
        float nm = g_deg[r] * w[e] * g_deg[c];    // g_deg holds dinv
        int pos = g_rowptr[c] + atomicAdd(&g_cnt[c], 1);
        g_epack[pos] = make_int2(r, __float_as_int(nm));
    }
}

// ---------------- 3xTF32 tensor-core GEMM: Y[M,128] = X[M,128] @ W[128,128] ----------------
// BM=128, 512 threads (16 warps). Warp tile m32 x n32 (2 m16-tiles x 4 n8-tiles).
// Explicit 2-stage software pipeline: prefetch k-step i+1 fragments (8 X floats +
// 4 W float4) into registers while step i's 24 MMAs execute — hides the 29cyc LDS
// latency at fixed (smem-capped) occupancy.
#define MMA_TF32(acc, a0, a1, a2, a3, b0, b1)                               \
    asm volatile(                                                           \
        "mma.sync.aligned.m16n8k8.row.col.f32.tf32.tf32.f32 "               \
        "{%0,%1,%2,%3},{%4,%5,%6,%7},{%8,%9},{%0,%1,%2,%3};\n"              \
        : "+f"(acc[0]), "+f"(acc[1]), "+f"(acc[2]), "+f"(acc[3])            \
        : "r"(a0), "r"(a1), "r"(a2), "r"(a3), "r"(b0), "r"(b1))

__device__ __forceinline__ void gemm_load(
    const float* __restrict__ Xs, const float* __restrict__ WFhi,
    const float* __restrict__ WFlo,
    int xb00, int xb01, int xb10, int xb11, int wbase, int kb,
    float* XD, float4& LA, float4& LB, float4& HA, float4& HB) {
    XD[0] = Xs[xb00 + kb];     XD[1] = Xs[xb01 + kb];
    XD[2] = Xs[xb00 + kb + 4]; XD[3] = Xs[xb01 + kb + 4];
    XD[4] = Xs[xb10 + kb];     XD[5] = Xs[xb11 + kb];
    XD[6] = Xs[xb10 + kb + 4]; XD[7] = Xs[xb11 + kb + 4];
    int wb = wbase + kb * 132;
    LA = *(const float4*)&WFlo[wb];
    LB = *(const float4*)&WFlo[wb + 528];
    HA = *(const float4*)&WFhi[wb];
    HB = *(const float4*)&WFhi[wb + 528];
}

__device__ __forceinline__ void gemm_step(
    const float* XD, float4 LA, float4 LB, float4 HA, float4 HB,
    float acc[2][4][4]) {
    uint32_t ah[2][4], al[2][4];
    tf32_split(XD[0], ah[0][0], al[0][0]);
    tf32_split(XD[1], ah[0][1], al[0][1]);
    tf32_split(XD[2], ah[0][2], al[0][2]);
    tf32_split(XD[3], ah[0][3], al[0][3]);
    tf32_split(XD[4], ah[1][0], al[1][0]);
    tf32_split(XD[5], ah[1][1], al[1][1]);
    tf32_split(XD[6], ah[1][2], al[1][2]);
    tf32_split(XD[7], ah[1][3], al[1][3]);
    uint32_t bl0[4] = {__float_as_uint(LA.x), __float_as_uint(LA.y),
                       __float_as_uint(LA.z), __float_as_uint(LA.w)};
    uint32_t bl1[4] = {__float_as_uint(LB.x), __float_as_uint(LB.y),
                       __float_as_uint(LB.z), __float_as_uint(LB.w)};
    uint32_t bh0[4] = {__float_as_uint(HA.x), __float_as_uint(HA.y),
                       __float_as_uint(HA.z), __float_as_uint(HA.w)};
    uint32_t bh1[4] = {__float_as_uint(HB.x), __float_as_uint(HB.y),
                       __float_as_uint(HB.z), __float_as_uint(HB.w)};
    #pragma unroll
    for (int mt = 0; mt < 2; ++mt) {
        #pragma unroll
        for (int nt = 0; nt < 4; ++nt) {
            MMA_TF32(acc[mt][nt], ah[mt][0], ah[mt][1], ah[mt][2], ah[mt][3],
                     bl0[nt], bl1[nt]);
            MMA_TF32(acc[mt][nt], al[mt][0], al[mt][1], al[mt][2], al[mt][3],
                     bh0[nt], bh1[nt]);
            MMA_TF32(acc[mt][nt], ah[mt][0], ah[mt][1], ah[mt][2], ah[mt][3],
                     bh0[nt], bh1[nt]);
        }
    }
}

__global__ void __launch_bounds__(512, 1)
k_gemm(const float* __restrict__ X, int layer, float* __restrict__ Y,
       const int* __restrict__ za, const int* __restrict__ zb,
       const float* __restrict__ ztab, int useEmbed) {
    extern __shared__ float sm[];
    float* Xs   = sm;                     // [128][132] = 16896 floats
    float* WFhi = sm + 16896;             // fragment-ready, 132-stride
    float* WFlo = WFhi + 16896;
    int tid = threadIdx.x;
    int row0 = blockIdx.x * 128;

    // prologue: straight float4 copy of pre-split W (4224 float4 each)
    {
        const float4* shi = (const float4*)(g_wfhi + layer * 16896);
        const float4* slo = (const float4*)(g_wflo + layer * 16896);
        float4* dhi = (float4*)WFhi;
        float4* dlo = (float4*)WFlo;
        for (int idx = tid; idx < 4224; idx += 512) {
            dhi[idx] = shi[idx];
            dlo[idx] = slo[idx];
        }
    }
    // load X tile (raw fp32); layer 0: X row = ztab[z[row]]
    const int* zsel = g_aIsBatch ? zb : za;
    #pragma unroll
    for (int i = 0; i < 8; ++i) {
        int idx = tid + i * 512;
        int m = idx >> 5, kv = idx & 31;
        int r = row0 + m;
        float4 v = make_float4(0.f, 0.f, 0.f, 0.f);
        if (r < NN) {
            const float4* src = useEmbed ? ((const float4*)ztab + (size_t)zsel[r] * 32)
                                         : ((const float4*)X + (size_t)r * 32);
            v = src[kv];
        }
        *(float4*)&Xs[m * 132 + kv * 4] = v;
    }
    __syncthreads();

    int wid = tid >> 5, lane = tid & 31;
    int m0 = (wid & 3) * 32;          // 4 m32 groups -> 128 rows
    int ng = wid >> 2;                // 0..3
    int n0 = ng * 32;                 // n32 per warp
    int g  = lane >> 2;               // 0..7
    int q  = lane & 3;                // 0..3

    float acc[2][4][4];
    #pragma unroll
    for (int mt = 0; mt < 2; ++mt)
        #pragma unroll
        for (int nt = 0; nt < 4; ++nt)
            #pragma unroll
            for (int j = 0; j < 4; ++j) acc[mt][nt][j] = 0.f;

    int xb00 = (m0 + g) * 132 + q;
    int xb01 = (m0 + 8 + g) * 132 + q;
    int xb10 = (m0 + 16 + g) * 132 + q;
    int xb11 = (m0 + 24 + g) * 132 + q;
    int wbase = q * 132 + g * 16 + ng * 4;

    // 2-stage pipelined mainloop, unrolled x2 (register sets A/B alternate)
    float xA[8], xB[8];
    float4 lA0, lB0, hA0, hB0, lA1, lB1, hA1, hB1;
    gemm_load(Xs, WFhi, WFlo, xb00, xb01, xb10, xb11, wbase, 0,
              xA, lA0, lB0, hA0, hB0);
    #pragma unroll
    for (int ks = 0; ks < 16; ks += 2) {
        gemm_load(Xs, WFhi, WFlo, xb00, xb01, xb10, xb11, wbase, (ks + 1) * 8,
                  xB, lA1, lB1, hA1, hB1);
        gemm_step(xA, lA0, lB0, hA0, hB0, acc);
        if (ks + 2 < 16)
            gemm_load(Xs, WFhi, WFlo, xb00, xb01, xb10, xb11, wbase, (ks + 2) * 8,
                      xA, lA0, lB0, hA0, hB0);
        gemm_step(xB, lA1, lB1, hA1, hB1, acc);
    }

    // store: c0,c1 -> (row, 2q),(row, 2q+1); c2,c3 -> row+8
    #pragma unroll
    for (int mt = 0; mt < 2; ++mt) {
        int r = row0 + m0 + mt * 16 + g;
        #pragma unroll
        for (int nt = 0; nt < 4; ++nt) {
            int cc = n0 + nt * 8 + 2 * q;
            if (r < NN)
                *(float2*)&Y[r * 128 + cc] = make_float2(acc[mt][nt][0], acc[mt][nt][1]);
            if (r + 8 < NN)
                *(float2*)&Y[(r + 8) * 128 + cc] = make_float2(acc[mt][nt][2], acc[mt][nt][3]);
        }
    }
}

// ---------------- CSR gather-aggregate + bias (+ReLU) fused ----------------
// one warp per node, one float4 per lane; 2-deep rotating software pipeline
__global__ void k_gather(const float* __restrict__ xw, const float* __restrict__ bias,
                         float* __restrict__ out, int do_relu) {
    int gtid = blockIdx.x * blockDim.x + threadIdx.x;
    int v = gtid >> 5;
    int lane = gtid & 31;
    if (v >= NN) return;

    const float4* xwv = (const float4*)xw;
    float di = g_deg[v];                 // holds dinv
    float s = di * di;                   // self-loop norm
    float4 acc = xwv[(size_t)v * 32 + lane];
    acc.x *= s; acc.y *= s; acc.z *= s; acc.w *= s;

    int p = g_rowptr[v], end = g_rowptr[v + 1];
    if (p < end) {
        int2 pr = g_epack[p];
        for (++p; p < end; ++p) {
            int2 nxt = g_epack[p];
            float nm = __int_as_float(pr.y);
            float4 xv = xwv[(size_t)pr.x * 32 + lane];
            acc.x += nm * xv.x; acc.y += nm * xv.y;
            acc.z += nm * xv.z; acc.w += nm * xv.w;
            pr = nxt;
        }
        float nm = __int_as_float(pr.y);
        float4 xv = xwv[(size_t)pr.x * 32 + lane];
        acc.x += nm * xv.x; acc.y += nm * xv.y;
        acc.z += nm * xv.z; acc.w += nm * xv.w;
    }

    float4 b = ((const float4*)bias)[lane];
    acc.x += b.x; acc.y += b.y; acc.z += b.z; acc.w += b.w;
    if (do_relu) {
        acc.x = fmaxf(acc.x, 0.f); acc.y = fmaxf(acc.y, 0.f);
        acc.z = fmaxf(acc.z, 0.f); acc.w = fmaxf(acc.w, 0.f);
    }
    ((float4*)out)[(size_t)v * 32 + lane] = acc;
}

// ---------------- readout ----------------
__global__ void k_readout(const float* __restrict__ X,
                          const int* __restrict__ cand_a, const int* __restrict__ cand_b,
                          const float* __restrict__ W1, const float* __restrict__ b1,
                          const float* __restrict__ W2, const float* __restrict__ b2,
                          float* __restrict__ out) {
    const int* batch = g_aIsBatch ? cand_a : cand_b;
    __shared__ float h[128];
    __shared__ int sc;
    __shared__ float red[4];
    int g = blockIdx.x, j = threadIdx.x;
    if (j == 0) {   // searchsorted: first idx with batch[idx] >= g
        int lo = 0, hi = NN;
        while (lo < hi) { int mid = (lo + hi) >> 1; if (batch[mid] < g) lo = mid + 1; else hi = mid; }
        sc = lo;
    }
    __syncthreads();
    int c = sc;
    h[j] = X[c * 128 + j] * X[(c + 1) * 128 + j];
    __syncthreads();
    float acc = b1[j];
    #pragma unroll 8
    for (int k = 0; k < 128; ++k) acc += h[k] * W1[k * 128 + j];
    acc = fmaxf(acc, 0.f);
    float v = acc * W2[j];
    #pragma unroll
    for (int o = 16; o; o >>= 1) v += __shfl_xor_sync(0xffffffffu, v, o);
    if ((j & 31) == 0) red[j >> 5] = v;
    __syncthreads();
    if (j == 0) out[g] = red[0] + red[1] + red[2] + red[3] + b2[0];
}

// ---------------- launch: bind inputs BY SIZE (metadata order is unknown) ----------------
extern "C" void kernel_launch(void* const* d_in, const int* in_sizes, int n_in,
                              void* d_out, int out_size) {
    const int* i100k[2] = {0, 0}; int n100k = 0;
    const void* v16k[4] = {0, 0, 0, 0}; int n16k = 0;
    const void* v128[8] = {0, 0, 0, 0, 0, 0, 0, 0}; int n128 = 0;
    const int*   ei = 0; const float* ew = 0; const float* ztab = 0;
    const float* packedW = 0; const float* packedB = 0; const float* lin2b = 0;

    for (int i = 0; i < n_in; ++i) {
        int s = in_sizes[i];
        if      (s == 2 * EE)      ei   = (const int*)d_in[i];
        else if (s == EE)          ew   = (const float*)d_in[i];
        else if (s == 1000 * HH)   ztab = (const float*)d_in[i];
        else if (s == NN)          { if (n100k < 2) i100k[n100k++] = (const int*)d_in[i]; }
        else if (s == HH * HH)     { if (n16k < 4) v16k[n16k++] = d_in[i]; }
        else if (s == 3 * HH * HH) packedW = (const float*)d_in[i];
        else if (s == HH)          { if (n128 < 8) v128[n128++] = d_in[i]; }
        else if (s == 3 * HH)      packedB = (const float*)d_in[i];
        else if (s == 1)           lin2b = (const float*)d_in[i];
    }

    const float* convW[3]; const float* convB[3];
    const float* lin1W; const float* lin1b; const float* lin2W;
    if (packedW) {
        convW[0] = packedW; convW[1] = packedW + HH * HH; convW[2] = packedW + 2 * HH * HH;
        lin1W = (const float*)v16k[0];
    } else {
        convW[0] = (const float*)v16k[0]; convW[1] = (const float*)v16k[1];
        convW[2] = (const float*)v16k[2]; lin1W = (const float*)v16k[3];
    }
    if (packedB) {
        convB[0] = packedB; convB[1] = packedB + HH; convB[2] = packedB + 2 * HH;
        lin1b = (const float*)v128[0]; lin2W = (const float*)v128[1];
    } else {
        convB[0] = (const float*)v128[0]; convB[1] = (const float*)v128[1];
        convB[2] = (const float*)v128[2];
        lin1b = (const float*)v128[3]; lin2W = (const float*)v128[4];
    }
    float* out = (float*)d_out;

    float *A, *B;
    cudaGetSymbolAddress((void**)&A, g_bufA);
    cudaGetSymbolAddress((void**)&B, g_bufB);

    const int SMEM = 3 * 16896 * 4;  // 202752: Xs + WFhi + WFlo
    cudaFuncSetAttribute(k_gemm, cudaFuncAttributeMaxDynamicSharedMemorySize, SMEM);

    const int TB = 256;
    int nblk_n  = (NN + TB - 1) / TB;         // 391
    int nblk_e  = (EE + TB - 1) / TB;         // 6250
    int nblk_nh = (NN * 32 + TB - 1) / TB;    // 12500
    int scan_blocks = (NN + 1023) / 1024;     // 98
    int gemm_blocks = (NN + 127) / 128;       // 782

    // launch 0: detect + W split + deg/cnt init (fused)
    k_detect<<<97 + 196, 512>>>(i100k[0], convW[0], convW[1], convW[2]);
    // launch 1,2
    k_count<<<nblk_e, TB>>>(ei, ew);
    k_scan1<<<scan_blocks, 1024>>>();         // also computes dinv

    // launch 3: layer-0 GEMM (embedding fused; independent of CSR) — stays in the
    // profiler's capture window.
    k_gemm<<<gemm_blocks, 512, SMEM>>>(A, 0, B, i100k[0], i100k[1], ztab, 1);

    // CSR build (rest)
    k_scan2<<<1, 128>>>(scan_blocks);
    k_scan3<<<nblk_n, TB>>>();
    k_fill <<<nblk_e, TB>>>(ei, ew);

    // layer 0 aggregate, then layers 1,2
    k_gather<<<nblk_nh, TB>>>(B, convB[0], A, 1);
    for (int l = 1; l < 3; ++l) {
        k_gemm  <<<gemm_blocks, 512, SMEM>>>(A, l, B, i100k[0], i100k[1], ztab, 0);
        k_gather<<<nblk_nh, TB>>>(B, convB[l], A, (l < 2) ? 1 : 0);
    }

    // readout
    k_readout<<<GG, 128>>>(A, i100k[0], i100k[1], lin1W, lin1b, lin2W, lin2b, out);
}

// round 15
// speedup vs baseline: 1.1891x; 1.1850x over previous
#include <cuda_runtime.h>
#include <cuda_bf16.h>
#include <cstdint>

#define NN 100000
#define EE 1600000
#define HH 128
#define GG 500

// ---------------- scratch (static __device__ globals; no allocation) ----------------
__device__ float g_bufA[NN * HH];     // ping
__device__ float g_bufB[NN * HH];     // pong (xw)
__device__ float g_deg[NN];           // deg -> dinv (in place)
__device__ int   g_cnt[NN];           // histogram / fill counter
__device__ int   g_rowptr[NN + 1];
__device__ int2  g_epack[EE];         // {row, norm-bits} per CSR-ordered edge
__device__ int   g_part[128];         // scan partials (98 used)
__device__ int   g_aIsBatch;          // input-disambiguation flag
__device__ float g_wfhi[3 * 17408];   // W hi tf32, [k*136+n] layout, per layer
__device__ float g_wflo[3 * 17408];   // W lo tf32
__device__ float g_ctr[2 * GG * HH];  // layer-2 center-node outputs (compact)

__device__ __forceinline__ void tf32_split(float x, uint32_t& hi, uint32_t& lo) {
    asm("cvt.rna.tf32.f32 %0, %1;" : "=r"(hi) : "f"(x));
    float r = x - __uint_as_float(hi);
    asm("cvt.rna.tf32.f32 %0, %1;" : "=r"(lo) : "f"(r));
}

// ---------------- detector + one-shot W split + deg init (fused: 1 launch) ----------------
// block 0: z/batch detect. blocks 1..96: split conv weights to [k*136+n] hi/lo gmem.
// blocks 97..292: init g_deg/g_cnt.
__global__ void k_detect(const int* __restrict__ a,
                         const float* __restrict__ w0, const float* __restrict__ w1,
                         const float* __restrict__ w2) {
    if (blockIdx.x == 0) {
        int i = threadIdx.x;                       // 512 threads
        int v  = a[i];
        int vp = (i > 0) ? a[i - 1] : 0;
        int ok = (v >= 0) && (v < GG) && (v >= vp);
        int all = __syncthreads_and(ok);
        if (i == 0) g_aIsBatch = all;
    } else if (blockIdx.x <= 96) {
        int idx = (blockIdx.x - 1) * 512 + threadIdx.x;   // 0..49151
        int layer = idx >> 14;
        int e = idx & 16383;
        int k = e >> 7, n = e & 127;
        const float* Wsel = (layer == 0) ? w0 : ((layer == 1) ? w1 : w2);
        uint32_t h, l;
        tf32_split(Wsel[k * 128 + n], h, l);
        int off = layer * 17408 + k * 136 + n;
        g_wfhi[off] = __uint_as_float(h);
        g_wflo[off] = __uint_as_float(l);
    } else {
        int i = (int)(blockIdx.x - 97) * 512 + threadIdx.x;
        if (i < NN) { g_deg[i] = 1.0f; g_cnt[i] = 0; }   // self-loop weight 1
    }
}

__global__ void k_count(const int* __restrict__ ei, const float* __restrict__ w) {
    int e = blockIdx.x * blockDim.x + threadIdx.x;
    if (e < EE) {
        int c = ei[EE + e];
        atomicAdd(&g_deg[c], w[e]);
        atomicAdd(&g_cnt[c], 1);
    }
}

// ---------------- CSR build (scan1 also computes dinv in place) ----------------
__global__ void k_scan1() {   // blocks of 1024 over g_cnt
    __shared__ int s[1024];
    int tid = threadIdx.x;
    int i = blockIdx.x * 1024 + tid;
    if (i < NN) { float d = g_deg[i]; g_deg[i] = (d > 0.f) ? rsqrtf(d) : 0.f; }
    int v = (i < NN) ? g_cnt[i] : 0;
    s[tid] = v; __syncthreads();
    #pragma unroll
    for (int off = 1; off < 1024; off <<= 1) {
        int t = (tid >= off) ? s[tid - off] : 0;
        __syncthreads();
        s[tid] += t; __syncthreads();
    }
    if (i < NN) g_rowptr[i] = s[tid] - v;         // exclusive within block
    if (tid == 1023) g_part[blockIdx.x] = s[1023];
}

__global__ void k_scan2(int nblocks) {   // one 128-thread block, parallel scan
    __shared__ int s[128];
    int tid = threadIdx.x;
    int v = (tid < nblocks) ? g_part[tid] : 0;
    s[tid] = v; __syncthreads();
    #pragma unroll
    for (int off = 1; off < 128; off <<= 1) {
        int t = (tid >= off) ? s[tid - off] : 0;
        __syncthreads();
        s[tid] += t; __syncthreads();
    }
    if (tid < nblocks) g_part[tid] = s[tid] - v;  // exclusive
    if (tid == 127) g_rowptr[NN] = s[127];
}

__global__ void k_scan3() {
    int i = blockIdx.x * blockDim.x + threadIdx.x;
    if (i < NN) { g_rowptr[i] += g_part[i >> 10]; g_cnt[i] = 0; }
}

// fused: CSR fill + norm computation + epack write (one edge pass)
__global__ void k_fill(const int* __restrict__ ei, const float* __restrict__ w) {
    int e = blockIdx.x * blockDim.x + threadIdx.x;
    if (e < EE) {
        int r = ei[e];
        int c = ei[EE + e];
        float nm = g_deg[r] * w[e] * g_deg[c];    // g_deg holds dinv
        int pos = g_rowptr[c] + atomicAdd(&g_cnt[c], 1);
        g_epack[pos] = make_int2(r, __float_as_int(nm));
    }
}

// ---------------- 3xTF32 tensor-core GEMM: Y[M,128] = X[M,128] @ W[128,128] ----------------
// R9 config: BM=128, 512 threads (16 warps). Warp tile m16 x n64 (8 n8 tiles), K=128.
// W hi/lo pre-split in gmem ([k*136+n] layout); prologue is a pure float4 copy.
// Layer 0 fuses the embedding lookup: X row r = ztab[z[r]].
#define MMA_TF32(acc, a0, a1, a2, a3, b0, b1)                               \
    asm volatile(                                                           \
        "mma.sync.aligned.m16n8k8.row.col.f32.tf32.tf32.f32 "               \
        "{%0,%1,%2,%3},{%4,%5,%6,%7},{%8,%9},{%0,%1,%2,%3};\n"              \
        : "+f"(acc[0]), "+f"(acc[1]), "+f"(acc[2]), "+f"(acc[3])            \
        : "r"(a0), "r"(a1), "r"(a2), "r"(a3), "r"(b0), "r"(b1))

__global__ void __launch_bounds__(512, 1)
k_gemm(const float* __restrict__ X, int layer, float* __restrict__ Y,
       const int* __restrict__ za, const int* __restrict__ zb,
       const float* __restrict__ ztab, int useEmbed) {
    extern __shared__ float sm[];
    float* Xs  = sm;                      // [128][132] = 16896 floats
    float* Whi = sm + 16896;              // [128][136] = 17408 floats
    float* Wlo = Whi + 17408;
    int tid = threadIdx.x;
    int row0 = blockIdx.x * 128;

    // prologue: pure float4 copy of pre-split W (4352 float4 each)
    {
        const float4* shi = (const float4*)(g_wfhi + layer * 17408);
        const float4* slo = (const float4*)(g_wflo + layer * 17408);
        float4* dhi = (float4*)Whi;
        float4* dlo = (float4*)Wlo;
        for (int idx = tid; idx < 4352; idx += 512) {
            dhi[idx] = shi[idx];
            dlo[idx] = slo[idx];
        }
    }
    // load X tile (raw fp32); layer 0: X row = ztab[z[row]]
    const int* zsel = g_aIsBatch ? zb : za;
    #pragma unroll
    for (int i = 0; i < 8; ++i) {
        int idx = tid + i * 512;
        int m = idx >> 5, kv = idx & 31;
        int r = row0 + m;
        float4 v = make_float4(0.f, 0.f, 0.f, 0.f);
        if (r < NN) {
            const float4* src = useEmbed ? ((const float4*)ztab + (size_t)zsel[r] * 32)
                                         : ((const float4*)X + (size_t)r * 32);
            v = src[kv];
        }
        *(float4*)&Xs[m * 132 + kv * 4] = v;
    }
    __syncthreads();

    int wid = tid >> 5, lane = tid & 31;
    int m0 = (wid & 7) * 16;          // 0..112 (m16 tile)
    int n0 = (wid >> 3) * 64;         // 0,64
    int g  = lane >> 2;               // 0..7
    int q  = lane & 3;                // 0..3

    float acc[8][4];
    #pragma unroll
    for (int nt = 0; nt < 8; ++nt)
        #pragma unroll
        for (int j = 0; j < 4; ++j) acc[nt][j] = 0.f;

    #pragma unroll 2
    for (int ks = 0; ks < 16; ++ks) {
        int kb = ks * 8;
        uint32_t ah[4], al[4];
        int rb = m0 + g;
        tf32_split(Xs[rb * 132 + kb + q],           ah[0], al[0]);
        tf32_split(Xs[(rb + 8) * 132 + kb + q],     ah[1], al[1]);
        tf32_split(Xs[rb * 132 + kb + q + 4],       ah[2], al[2]);
        tf32_split(Xs[(rb + 8) * 132 + kb + q + 4], ah[3], al[3]);
        #pragma unroll
        for (int nt = 0; nt < 8; ++nt) {
            int nc = n0 + nt * 8 + g;
            uint32_t bh0 = __float_as_uint(Whi[(kb + q) * 136 + nc]);
            uint32_t bl0 = __float_as_uint(Wlo[(kb + q) * 136 + nc]);
            uint32_t bh1 = __float_as_uint(Whi[(kb + q + 4) * 136 + nc]);
            uint32_t bl1 = __float_as_uint(Wlo[(kb + q + 4) * 136 + nc]);
            MMA_TF32(acc[nt], ah[0], ah[1], ah[2], ah[3], bl0, bl1);
            MMA_TF32(acc[nt], al[0], al[1], al[2], al[3], bh0, bh1);
            MMA_TF32(acc[nt], ah[0], ah[1], ah[2], ah[3], bh0, bh1);
        }
    }

    // store: c0,c1 -> (row, 2q),(row, 2q+1); c2,c3 -> row+8
    {
        int r = row0 + m0 + g;
        #pragma unroll
        for (int nt = 0; nt < 8; ++nt) {
            int cc = n0 + nt * 8 + 2 * q;
            if (r < NN)
                *(float2*)&Y[r * 128 + cc] = make_float2(acc[nt][0], acc[nt][1]);
            if (r + 8 < NN)
                *(float2*)&Y[(r + 8) * 128 + cc] = make_float2(acc[nt][2], acc[nt][3]);
        }
    }
}

// ---------------- CSR gather-aggregate + bias (+ReLU) fused (layers 0,1) ----------------
// one warp per node, one float4 per lane; 2-deep rotating software pipeline
__global__ void k_gather(const float* __restrict__ xw, const float* __restrict__ bias,
                         float* __restrict__ out, int do_relu) {
    int gtid = blockIdx.x * blockDim.x + threadIdx.x;
    int v = gtid >> 5;
    int lane = gtid & 31;
    if (v >= NN) return;

    const float4* xwv = (const float4*)xw;
    float di = g_deg[v];                 // holds dinv
    float s = di * di;                   // self-loop norm
    float4 acc = xwv[(size_t)v * 32 + lane];
    acc.x *= s; acc.y *= s; acc.z *= s; acc.w *= s;

    int p = g_rowptr[v], end = g_rowptr[v + 1];
    if (p < end) {
        int2 pr = g_epack[p];
        for (++p; p < end; ++p) {
            int2 nxt = g_epack[p];
            float nm = __int_as_float(pr.y);
            float4 xv = xwv[(size_t)pr.x * 32 + lane];
            acc.x += nm * xv.x; acc.y += nm * xv.y;
            acc.z += nm * xv.z; acc.w += nm * xv.w;
            pr = nxt;
        }
        float nm = __int_as_float(pr.y);
        float4 xv = xwv[(size_t)pr.x * 32 + lane];
        acc.x += nm * xv.x; acc.y += nm * xv.y;
        acc.z += nm * xv.z; acc.w += nm * xv.w;
    }

    float4 b = ((const float4*)bias)[lane];
    acc.x += b.x; acc.y += b.y; acc.z += b.z; acc.w += b.w;
    if (do_relu) {
        acc.x = fmaxf(acc.x, 0.f); acc.y = fmaxf(acc.y, 0.f);
        acc.z = fmaxf(acc.z, 0.f); acc.w = fmaxf(acc.w, 0.f);
    }
    ((float4*)out)[(size_t)v * 32 + lane] = acc;
}

// ---------------- layer-2 CENTER-ONLY gather: only 2*GG nodes are ever read ----------------
// warp w -> graph g = w>>1, node = searchsorted(batch, g) + (w&1). Output compact g_ctr.
__global__ void k_gather_ctr(const float* __restrict__ xw, const float* __restrict__ bias,
                             const int* __restrict__ cand_a, const int* __restrict__ cand_b,
                             float* __restrict__ outc) {
    const int* batch = g_aIsBatch ? cand_a : cand_b;
    int gtid = blockIdx.x * blockDim.x + threadIdx.x;
    int w = gtid >> 5;
    int lane = gtid & 31;
    if (w >= 2 * GG) return;
    int gph = w >> 1, idx = w & 1;

    int c = 0;
    if (lane == 0) {   // searchsorted: first i with batch[i] >= gph
        int lo = 0, hi = NN;
        while (lo < hi) { int mid = (lo + hi) >> 1; if (batch[mid] < gph) lo = mid + 1; else hi = mid; }
        c = lo;
    }
    c = __shfl_sync(0xffffffffu, c, 0);
    int v = c + idx;

    const float4* xwv = (const float4*)xw;
    float di = g_deg[v];
    float s = di * di;
    float4 acc = xwv[(size_t)v * 32 + lane];
    acc.x *= s; acc.y *= s; acc.z *= s; acc.w *= s;

    int p = g_rowptr[v], end = g_rowptr[v + 1];
    for (; p < end; ++p) {
        int2 e = g_epack[p];
        float nm = __int_as_float(e.y);
        float4 xv = xwv[(size_t)e.x * 32 + lane];
        acc.x += nm * xv.x; acc.y += nm * xv.y;
        acc.z += nm * xv.z; acc.w += nm * xv.w;
    }
    float4 b = ((const float4*)bias)[lane];
    acc.x += b.x; acc.y += b.y; acc.z += b.z; acc.w += b.w;
    ((float4*)outc)[w * 32 + lane] = acc;   // no relu on last conv layer
}

// ---------------- readout (reads compact center buffer) ----------------
__global__ void k_readout(const float* __restrict__ C,
                          const float* __restrict__ W1, const float* __restrict__ b1,
                          const float* __restrict__ W2, const float* __restrict__ b2,
                          float* __restrict__ out) {
    __shared__ float h[128];
    __shared__ float red[4];
    int g = blockIdx.x, j = threadIdx.x;
    h[j] = C[(2 * g) * 128 + j] * C[(2 * g + 1) * 128 + j];
    __syncthreads();
    float acc = b1[j];
    #pragma unroll 8
    for (int k = 0; k < 128; ++k) acc += h[k] * W1[k * 128 + j];
    acc = fmaxf(acc, 0.f);
    float v = acc * W2[j];
    #pragma unroll
    for (int o = 16; o; o >>= 1) v += __shfl_xor_sync(0xffffffffu, v, o);
    if ((j & 31) == 0) red[j >> 5] = v;
    __syncthreads();
    if (j == 0) out[g] = red[0] + red[1] + red[2] + red[3] + b2[0];
}

// ---------------- launch: bind inputs BY SIZE (metadata order is unknown) ----------------
extern "C" void kernel_launch(void* const* d_in, const int* in_sizes, int n_in,
                              void* d_out, int out_size) {
    const int* i100k[2] = {0, 0}; int n100k = 0;
    const void* v16k[4] = {0, 0, 0, 0}; int n16k = 0;
    const void* v128[8] = {0, 0, 0, 0, 0, 0, 0, 0}; int n128 = 0;
    const int*   ei = 0; const float* ew = 0; const float* ztab = 0;
    const float* packedW = 0; const float* packedB = 0; const float* lin2b = 0;

    for (int i = 0; i < n_in; ++i) {
        int s = in_sizes[i];
        if      (s == 2 * EE)      ei   = (const int*)d_in[i];
        else if (s == EE)          ew   = (const float*)d_in[i];
        else if (s == 1000 * HH)   ztab = (const float*)d_in[i];
        else if (s == NN)          { if (n100k < 2) i100k[n100k++] = (const int*)d_in[i]; }
        else if (s == HH * HH)     { if (n16k < 4) v16k[n16k++] = d_in[i]; }
        else if (s == 3 * HH * HH) packedW = (const float*)d_in[i];
        else if (s == HH)          { if (n128 < 8) v128[n128++] = d_in[i]; }
        else if (s == 3 * HH)      packedB = (const float*)d_in[i];
        else if (s == 1)           lin2b = (const float*)d_in[i];
    }

    const float* convW[3]; const float* convB[3];
    const float* lin1W; const float* lin1b; const float* lin2W;
    if (packedW) {
        convW[0] = packedW; convW[1] = packedW + HH * HH; convW[2] = packedW + 2 * HH * HH;
        lin1W = (const float*)v16k[0];
    } else {
        convW[0] = (const float*)v16k[0]; convW[1] = (const float*)v16k[1];
        convW[2] = (const float*)v16k[2]; lin1W = (const float*)v16k[3];
    }
    if (packedB) {
        convB[0] = packedB; convB[1] = packedB + HH; convB[2] = packedB + 2 * HH;
        lin1b = (const float*)v128[0]; lin2W = (const float*)v128[1];
    } else {
        convB[0] = (const float*)v128[0]; convB[1] = (const float*)v128[1];
        convB[2] = (const float*)v128[2];
        lin1b = (const float*)v128[3]; lin2W = (const float*)v128[4];
    }
    float* out = (float*)d_out;

    float *A, *B, *C;
    cudaGetSymbolAddress((void**)&A, g_bufA);
    cudaGetSymbolAddress((void**)&B, g_bufB);
    cudaGetSymbolAddress((void**)&C, g_ctr);

    const int SMEM = (16896 + 2 * 17408) * 4;  // 206848: Xs + Whi + Wlo
    cudaFuncSetAttribute(k_gemm, cudaFuncAttributeMaxDynamicSharedMemorySize, SMEM);

    const int TB = 256;
    int nblk_n  = (NN + TB - 1) / TB;         // 391
    int nblk_e  = (EE + TB - 1) / TB;         // 6250
    int nblk_nh = (NN * 32 + TB - 1) / TB;    // 12500
    int scan_blocks = (NN + 1023) / 1024;     // 98
    int gemm_blocks = (NN + 127) / 128;       // 782

    // launch 0: detect + W split + deg/cnt init (fused)
    k_detect<<<97 + 196, 512>>>(i100k[0], convW[0], convW[1], convW[2]);
    // launch 1,2
    k_count<<<nblk_e, TB>>>(ei, ew);
    k_scan1<<<scan_blocks, 1024>>>();         // also computes dinv

    // launch 3: layer-0 GEMM (embedding fused; independent of CSR) — stays in the
    // profiler's capture window.
    k_gemm<<<gemm_blocks, 512, SMEM>>>(A, 0, B, i100k[0], i100k[1], ztab, 1);

    // CSR build (rest)
    k_scan2<<<1, 128>>>(scan_blocks);
    k_scan3<<<nblk_n, TB>>>();
    k_fill <<<nblk_e, TB>>>(ei, ew);

    // layer 0 aggregate (full, relu)
    k_gather<<<nblk_nh, TB>>>(B, convB[0], A, 1);
    // layer 1: gemm + full gather (relu)
    k_gemm  <<<gemm_blocks, 512, SMEM>>>(A, 1, B, i100k[0], i100k[1], ztab, 0);
    k_gather<<<nblk_nh, TB>>>(B, convB[1], A, 1);
    // layer 2: gemm + CENTER-ONLY gather (only 1000 rows are ever read)
    k_gemm  <<<gemm_blocks, 512, SMEM>>>(A, 2, B, i100k[0], i100k[1], ztab, 0);
    k_gather_ctr<<<(2 * GG * 32 + TB - 1) / TB, TB>>>(B, convB[2], i100k[0], i100k[1], C);

    // readout
    k_readout<<<GG, 128>>>(C, lin1W, lin1b, lin2W, lin2b, out);
}

// round 16
// speedup vs baseline: 1.3762x; 1.1573x over previous
#include <cuda_runtime.h>
#include <cuda_bf16.h>
#include <cstdint>

#define NN 100000
#define EE 1600000
#define HH 128
#define GG 500

// ---------------- scratch (static __device__ globals; no allocation) ----------------
__device__ float g_bufA[NN * HH];     // ping
__device__ float g_bufB[NN * HH];     // pong (xw)
__device__ float g_deg[NN];           // deg -> dinv (in place)
__device__ int   g_cnt[NN];           // histogram / fill counter
__device__ int   g_rowptr[NN + 1];
__device__ int2  g_epack[EE];         // {row, norm-bits} per CSR-ordered edge
__device__ int   g_part[128];         // scan partials (98 used)
__device__ int   g_aIsBatch;          // input-disambiguation flag
__device__ float g_wfhi[3 * 17408];   // W hi tf32, [k*136+n] layout, per layer
__device__ float g_wflo[3 * 17408];   // W lo tf32
__device__ float g_ctragg[2 * GG * HH]; // center aggregates of layer-1 output
__device__ float g_ctr[2 * GG * HH];    // layer-2 center outputs (compact)

__device__ __forceinline__ void tf32_split(float x, uint32_t& hi, uint32_t& lo) {
    asm("cvt.rna.tf32.f32 %0, %1;" : "=r"(hi) : "f"(x));
    float r = x - __uint_as_float(hi);
    asm("cvt.rna.tf32.f32 %0, %1;" : "=r"(lo) : "f"(r));
}

// ---------------- detector + one-shot W split + deg init (fused: 1 launch) ----------------
__global__ void k_detect(const int* __restrict__ a,
                         const float* __restrict__ w0, const float* __restrict__ w1,
                         const float* __restrict__ w2) {
    if (blockIdx.x == 0) {
        int i = threadIdx.x;                       // 512 threads
        int v  = a[i];
        int vp = (i > 0) ? a[i - 1] : 0;
        int ok = (v >= 0) && (v < GG) && (v >= vp);
        int all = __syncthreads_and(ok);
        if (i == 0) g_aIsBatch = all;
    } else if (blockIdx.x <= 96) {
        int idx = (blockIdx.x - 1) * 512 + threadIdx.x;   // 0..49151
        int layer = idx >> 14;
        int e = idx & 16383;
        int k = e >> 7, n = e & 127;
        const float* Wsel = (layer == 0) ? w0 : ((layer == 1) ? w1 : w2);
        uint32_t h, l;
        tf32_split(Wsel[k * 128 + n], h, l);
        int off = layer * 17408 + k * 136 + n;
        g_wfhi[off] = __uint_as_float(h);
        g_wflo[off] = __uint_as_float(l);
    } else {
        int i = (int)(blockIdx.x - 97) * 512 + threadIdx.x;
        if (i < NN) { g_deg[i] = 1.0f; g_cnt[i] = 0; }   // self-loop weight 1
    }
}

__global__ void k_count(const int* __restrict__ ei, const float* __restrict__ w) {
    int e = blockIdx.x * blockDim.x + threadIdx.x;
    if (e < EE) {
        int c = ei[EE + e];
        atomicAdd(&g_deg[c], w[e]);
        atomicAdd(&g_cnt[c], 1);
    }
}

// ---------------- CSR build (scan1 also computes dinv in place) ----------------
__global__ void k_scan1() {   // blocks of 1024 over g_cnt
    __shared__ int s[1024];
    int tid = threadIdx.x;
    int i = blockIdx.x * 1024 + tid;
    if (i < NN) { float d = g_deg[i]; g_deg[i] = (d > 0.f) ? rsqrtf(d) : 0.f; }
    int v = (i < NN) ? g_cnt[i] : 0;
    s[tid] = v; __syncthreads();
    #pragma unroll
    for (int off = 1; off < 1024; off <<= 1) {
        int t = (tid >= off) ? s[tid - off] : 0;
        __syncthreads();
        s[tid] += t; __syncthreads();
    }
    if (i < NN) g_rowptr[i] = s[tid] - v;         // exclusive within block
    if (tid == 1023) g_part[blockIdx.x] = s[1023];
}

__global__ void k_scan2(int nblocks) {   // one 128-thread block, parallel scan
    __shared__ int s[128];
    int tid = threadIdx.x;
    int v = (tid < nblocks) ? g_part[tid] : 0;
    s[tid] = v; __syncthreads();
    #pragma unroll
    for (int off = 1; off < 128; off <<= 1) {
        int t = (tid >= off) ? s[tid - off] : 0;
        __syncthreads();
        s[tid] += t; __syncthreads();
    }
    if (tid < nblocks) g_part[tid] = s[tid] - v;  // exclusive
    if (tid == 127) g_rowptr[NN] = s[127];
}

__global__ void k_scan3() {
    int i = blockIdx.x * blockDim.x + threadIdx.x;
    if (i < NN) { g_rowptr[i] += g_part[i >> 10]; g_cnt[i] = 0; }
}

// fused: CSR fill + norm computation + epack write (one edge pass)
__global__ void k_fill(const int* __restrict__ ei, const float* __restrict__ w) {
    int e = blockIdx.x * blockDim.x + threadIdx.x;
    if (e < EE) {
        int r = ei[e];
        int c = ei[EE + e];
        float nm = g_deg[r] * w[e] * g_deg[c];    // g_deg holds dinv
        int pos = g_rowptr[c] + atomicAdd(&g_cnt[c], 1);
        g_epack[pos] = make_int2(r, __float_as_int(nm));
    }
}

// ---------------- 3xTF32 tensor-core GEMM: Y[rows,128] = X[rows,128] @ W[128,128] ----------------
// R9 config: BM=128, 512 threads (16 warps), warp tile m16 x n64, K=128.
// W hi/lo pre-split in gmem; prologue is a pure float4 copy. Optional fused bias.
// Layer 0 fuses the embedding lookup: X row r = ztab[z[r]].
#define MMA_TF32(acc, a0, a1, a2, a3, b0, b1)                               \
    asm volatile(                                                           \
        "mma.sync.aligned.m16n8k8.row.col.f32.tf32.tf32.f32 "               \
        "{%0,%1,%2,%3},{%4,%5,%6,%7},{%8,%9},{%0,%1,%2,%3};\n"              \
        : "+f"(acc[0]), "+f"(acc[1]), "+f"(acc[2]), "+f"(acc[3])            \
        : "r"(a0), "r"(a1), "r"(a2), "r"(a3), "r"(b0), "r"(b1))

__global__ void __launch_bounds__(512, 1)
k_gemm(const float* __restrict__ X, int layer, float* __restrict__ Y,
       const int* __restrict__ za, const int* __restrict__ zb,
       const float* __restrict__ ztab, int useEmbed, int rows,
       const float* __restrict__ bias) {
    extern __shared__ float sm[];
    float* Xs  = sm;                      // [128][132] = 16896 floats
    float* Whi = sm + 16896;              // [128][136] = 17408 floats
    float* Wlo = Whi + 17408;
    int tid = threadIdx.x;
    int row0 = blockIdx.x * 128;

    // prologue: pure float4 copy of pre-split W (4352 float4 each)
    {
        const float4* shi = (const float4*)(g_wfhi + layer * 17408);
        const float4* slo = (const float4*)(g_wflo + layer * 17408);
        float4* dhi = (float4*)Whi;
        float4* dlo = (float4*)Wlo;
        for (int idx = tid; idx < 4352; idx += 512) {
            dhi[idx] = shi[idx];
            dlo[idx] = slo[idx];
        }
    }
    // load X tile (raw fp32); layer 0: X row = ztab[z[row]]
    const int* zsel = g_aIsBatch ? zb : za;
    #pragma unroll
    for (int i = 0; i < 8; ++i) {
        int idx = tid + i * 512;
        int m = idx >> 5, kv = idx & 31;
        int r = row0 + m;
        float4 v = make_float4(0.f, 0.f, 0.f, 0.f);
        if (r < rows) {
            const float4* src = useEmbed ? ((const float4*)ztab + (size_t)zsel[r] * 32)
                                         : ((const float4*)X + (size_t)r * 32);
            v = src[kv];
        }
        *(float4*)&Xs[m * 132 + kv * 4] = v;
    }
    __syncthreads();

    int wid = tid >> 5, lane = tid & 31;
    int m0 = (wid & 7) * 16;          // 0..112 (m16 tile)
    int n0 = (wid >> 3) * 64;         // 0,64
    int g  = lane >> 2;               // 0..7
    int q  = lane & 3;                // 0..3

    float acc[8][4];
    #pragma unroll
    for (int nt = 0; nt < 8; ++nt)
        #pragma unroll
        for (int j = 0; j < 4; ++j) acc[nt][j] = 0.f;

    #pragma unroll 2
    for (int ks = 0; ks < 16; ++ks) {
        int kb = ks * 8;
        uint32_t ah[4], al[4];
        int rb = m0 + g;
        tf32_split(Xs[rb * 132 + kb + q],           ah[0], al[0]);
        tf32_split(Xs[(rb + 8) * 132 + kb + q],     ah[1], al[1]);
        tf32_split(Xs[rb * 132 + kb + q + 4],       ah[2], al[2]);
        tf32_split(Xs[(rb + 8) * 132 + kb + q + 4], ah[3], al[3]);
        #pragma unroll
        for (int nt = 0; nt < 8; ++nt) {
            int nc = n0 + nt * 8 + g;
            uint32_t bh0 = __float_as_uint(Whi[(kb + q) * 136 + nc]);
            uint32_t bl0 = __float_as_uint(Wlo[(kb + q) * 136 + nc]);
            uint32_t bh1 = __float_as_uint(Whi[(kb + q + 4) * 136 + nc]);
            uint32_t bl1 = __float_as_uint(Wlo[(kb + q + 4) * 136 + nc]);
            MMA_TF32(acc[nt], ah[0], ah[1], ah[2], ah[3], bl0, bl1);
            MMA_TF32(acc[nt], al[0], al[1], al[2], al[3], bh0, bh1);
            MMA_TF32(acc[nt], ah[0], ah[1], ah[2], ah[3], bh0, bh1);
        }
    }

    // store: c0,c1 -> (row, 2q),(row, 2q+1); c2,c3 -> row+8; optional fused bias
    {
        int r = row0 + m0 + g;
        #pragma unroll
        for (int nt = 0; nt < 8; ++nt) {
            int cc = n0 + nt * 8 + 2 * q;
            float2 bb = make_float2(0.f, 0.f);
            if (bias) bb = *(const float2*)&bias[cc];
            if (r < rows)
                *(float2*)&Y[r * 128 + cc] =
                    make_float2(acc[nt][0] + bb.x, acc[nt][1] + bb.y);
            if (r + 8 < rows)
                *(float2*)&Y[(r + 8) * 128 + cc] =
                    make_float2(acc[nt][2] + bb.x, acc[nt][3] + bb.y);
        }
    }
}

// ---------------- CSR gather-aggregate + bias (+ReLU) fused (layers 0,1) ----------------
// one warp per node, one float4 per lane; 2-deep rotating software pipeline
__global__ void k_gather(const float* __restrict__ xw, const float* __restrict__ bias,
                         float* __restrict__ out, int do_relu) {
    int gtid = blockIdx.x * blockDim.x + threadIdx.x;
    int v = gtid >> 5;
    int lane = gtid & 31;
    if (v >= NN) return;

    const float4* xwv = (const float4*)xw;
    float di = g_deg[v];                 // holds dinv
    float s = di * di;                   // self-loop norm
    float4 acc = xwv[(size_t)v * 32 + lane];
    acc.x *= s; acc.y *= s; acc.z *= s; acc.w *= s;

    int p = g_rowptr[v], end = g_rowptr[v + 1];
    if (p < end) {
        int2 pr = g_epack[p];
        for (++p; p < end; ++p) {
            int2 nxt = g_epack[p];
            float nm = __int_as_float(pr.y);
            float4 xv = xwv[(size_t)pr.x * 32 + lane];
            acc.x += nm * xv.x; acc.y += nm * xv.y;
            acc.z += nm * xv.z; acc.w += nm * xv.w;
            pr = nxt;
        }
        float nm = __int_as_float(pr.y);
        float4 xv = xwv[(size_t)pr.x * 32 + lane];
        acc.x += nm * xv.x; acc.y += nm * xv.y;
        acc.z += nm * xv.z; acc.w += nm * xv.w;
    }

    float4 b = ((const float4*)bias)[lane];
    acc.x += b.x; acc.y += b.y; acc.z += b.z; acc.w += b.w;
    if (do_relu) {
        acc.x = fmaxf(acc.x, 0.f); acc.y = fmaxf(acc.y, 0.f);
        acc.z = fmaxf(acc.z, 0.f); acc.w = fmaxf(acc.w, 0.f);
    }
    ((float4*)out)[(size_t)v * 32 + lane] = acc;
}

// ---------------- layer-2 CENTER-ONLY aggregate of raw features (GEMM commuted out) ----------
// warp w -> graph g = w>>1, node = searchsorted(batch, g) + (w&1).
// outc[w] = self_norm*x[v] + sum norm*x[row]   (NO weights/bias; GEMM applied after)
__global__ void k_gather_ctr(const float* __restrict__ x,
                             const int* __restrict__ cand_a, const int* __restrict__ cand_b,
                             float* __restrict__ outc) {
    const int* batch = g_aIsBatch ? cand_a : cand_b;
    int gtid = blockIdx.x * blockDim.x + threadIdx.x;
    int w = gtid >> 5;
    int lane = gtid & 31;
    if (w >= 2 * GG) return;
    int gph = w >> 1, idx = w & 1;

    int c = 0;
    if (lane == 0) {   // searchsorted: first i with batch[i] >= gph
        int lo = 0, hi = NN;
        while (lo < hi) { int mid = (lo + hi) >> 1; if (batch[mid] < gph) lo = mid + 1; else hi = mid; }
        c = lo;
    }
    c = __shfl_sync(0xffffffffu, c, 0);
    int v = c + idx;

    const float4* xv4 = (const float4*)x;
    float di = g_deg[v];
    float s = di * di;
    float4 acc = xv4[(size_t)v * 32 + lane];
    acc.x *= s; acc.y *= s; acc.z *= s; acc.w *= s;

    int p = g_rowptr[v], end = g_rowptr[v + 1];
    for (; p < end; ++p) {
        int2 e = g_epack[p];
        float nm = __int_as_float(e.y);
        float4 xv = xv4[(size_t)e.x * 32 + lane];
        acc.x += nm * xv.x; acc.y += nm * xv.y;
        acc.z += nm * xv.z; acc.w += nm * xv.w;
    }
    ((float4*)outc)[w * 32 + lane] = acc;
}

// ---------------- readout (reads compact center buffer) ----------------
__global__ void k_readout(const float* __restrict__ C,
                          const float* __restrict__ W1, const float* __restrict__ b1,
                          const float* __restrict__ W2, const float* __restrict__ b2,
                          float* __restrict__ out) {
    __shared__ float h[128];
    __shared__ float red[4];
    int g = blockIdx.x, j = threadIdx.x;
    h[j] = C[(2 * g) * 128 + j] * C[(2 * g + 1) * 128 + j];
    __syncthreads();
    float acc = b1[j];
    #pragma unroll 8
    for (int k = 0; k < 128; ++k) acc += h[k] * W1[k * 128 + j];
    acc = fmaxf(acc, 0.f);
    float v = acc * W2[j];
    #pragma unroll
    for (int o = 16; o; o >>= 1) v += __shfl_xor_sync(0xffffffffu, v, o);
    if ((j & 31) == 0) red[j >> 5] = v;
    __syncthreads();
    if (j == 0) out[g] = red[0] + red[1] + red[2] + red[3] + b2[0];
}

// ---------------- launch: bind inputs BY SIZE (metadata order is unknown) ----------------
extern "C" void kernel_launch(void* const* d_in, const int* in_sizes, int n_in,
                              void* d_out, int out_size) {
    const int* i100k[2] = {0, 0}; int n100k = 0;
    const void* v16k[4] = {0, 0, 0, 0}; int n16k = 0;
    const void* v128[8] = {0, 0, 0, 0, 0, 0, 0, 0}; int n128 = 0;
    const int*   ei = 0; const float* ew = 0; const float* ztab = 0;
    const float* packedW = 0; const float* packedB = 0; const float* lin2b = 0;

    for (int i = 0; i < n_in; ++i) {
        int s = in_sizes[i];
        if      (s == 2 * EE)      ei   = (const int*)d_in[i];
        else if (s == EE)          ew   = (const float*)d_in[i];
        else if (s == 1000 * HH)   ztab = (const float*)d_in[i];
        else if (s == NN)          { if (n100k < 2) i100k[n100k++] = (const int*)d_in[i]; }
        else if (s == HH * HH)     { if (n16k < 4) v16k[n16k++] = d_in[i]; }
        else if (s == 3 * HH * HH) packedW = (const float*)d_in[i];
        else if (s == HH)          { if (n128 < 8) v128[n128++] = d_in[i]; }
        else if (s == 3 * HH)      packedB = (const float*)d_in[i];
        else if (s == 1)           lin2b = (const float*)d_in[i];
    }

    const float* convW[3]; const float* convB[3];
    const float* lin1W; const float* lin1b; const float* lin2W;
    if (packedW) {
        convW[0] = packedW; convW[1] = packedW + HH * HH; convW[2] = packedW + 2 * HH * HH;
        lin1W = (const float*)v16k[0];
    } else {
        convW[0] = (const float*)v16k[0]; convW[1] = (const float*)v16k[1];
        convW[2] = (const float*)v16k[2]; lin1W = (const float*)v16k[3];
    }
    if (packedB) {
        convB[0] = packedB; convB[1] = packedB + HH; convB[2] = packedB + 2 * HH;
        lin1b = (const float*)v128[0]; lin2W = (const float*)v128[1];
    } else {
        convB[0] = (const float*)v128[0]; convB[1] = (const float*)v128[1];
        convB[2] = (const float*)v128[2];
        lin1b = (const float*)v128[3]; lin2W = (const float*)v128[4];
    }
    float* out = (float*)d_out;

    float *A, *B, *CA, *C;
    cudaGetSymbolAddress((void**)&A, g_bufA);
    cudaGetSymbolAddress((void**)&B, g_bufB);
    cudaGetSymbolAddress((void**)&CA, g_ctragg);
    cudaGetSymbolAddress((void**)&C, g_ctr);

    const int SMEM = (16896 + 2 * 17408) * 4;  // 206848: Xs + Whi + Wlo
    cudaFuncSetAttribute(k_gemm, cudaFuncAttributeMaxDynamicSharedMemorySize, SMEM);

    const int TB = 256;
    int nblk_n  = (NN + TB - 1) / TB;         // 391
    int nblk_e  = (EE + TB - 1) / TB;         // 6250
    int nblk_nh = (NN * 32 + TB - 1) / TB;    // 12500
    int scan_blocks = (NN + 1023) / 1024;     // 98
    int gemm_blocks = (NN + 127) / 128;       // 782

    // launch 0: detect + W split + deg/cnt init (fused)
    k_detect<<<97 + 196, 512>>>(i100k[0], convW[0], convW[1], convW[2]);
    // launch 1,2
    k_count<<<nblk_e, TB>>>(ei, ew);
    k_scan1<<<scan_blocks, 1024>>>();         // also computes dinv

    // launch 3: layer-0 GEMM (embedding fused; independent of CSR) — stays in the
    // profiler's capture window.
    k_gemm<<<gemm_blocks, 512, SMEM>>>(A, 0, B, i100k[0], i100k[1], ztab, 1, NN, 0);

    // CSR build (rest)
    k_scan2<<<1, 128>>>(scan_blocks);
    k_scan3<<<nblk_n, TB>>>();
    k_fill <<<nblk_e, TB>>>(ei, ew);

    // layer 0 aggregate (full, relu)
    k_gather<<<nblk_nh, TB>>>(B, convB[0], A, 1);
    // layer 1: gemm + full gather (relu)
    k_gemm  <<<gemm_blocks, 512, SMEM>>>(A, 1, B, i100k[0], i100k[1], ztab, 0, NN, 0);
    k_gather<<<nblk_nh, TB>>>(B, convB[1], A, 1);
    // layer 2 (GEMM commuted past aggregation): center aggregate of A, then
    // a 1000-row GEMM with fused bias -> compact center outputs.
    k_gather_ctr<<<(2 * GG * 32 + TB - 1) / TB, TB>>>(A, i100k[0], i100k[1], CA);
    k_gemm<<<(2 * GG + 127) / 128, 512, SMEM>>>(CA, 2, C, i100k[0], i100k[1], ztab, 0,
                                                2 * GG, convB[2]);

    // readout
    k_readout<<<GG, 128>>>(C, lin1W, lin1b, lin2W, lin2b, out);
}

// round 17
// speedup vs baseline: 1.8291x; 1.3291x over previous
#include <cuda_runtime.h>
#include <cuda_bf16.h>
#include <cstdint>

#define NN 100000
#define EE 1600000
#define HH 128
#define GG 500
#define CAP 40960   // compact S1 capacity (E[|S1|] ~ 17k, sigma ~ 130)

// ---------------- scratch (static __device__ globals; no allocation) ----------------
__device__ float g_bufA[NN * HH];     // ping (x0)
__device__ float g_bufB[NN * HH];     // pong (xw / compact buffers)
__device__ float g_deg[NN];           // deg -> dinv (in place)
__device__ int   g_cnt[NN];           // histogram / fill counter
__device__ int   g_rowptr[NN + 1];
__device__ int2  g_epack[EE];         // {row, norm-bits} per CSR-ordered edge
__device__ int   g_part[128];         // scan partials (98 used)
__device__ int   g_aIsBatch;          // input-disambiguation flag
__device__ float g_wfhi[3 * 17408];   // W hi tf32, [k*136+n] layout, per layer
__device__ float g_wflo[3 * 17408];   // W lo tf32
__device__ float g_ctragg[2 * GG * HH]; // center aggregates of compact x1
__device__ float g_ctr[2 * GG * HH];    // layer-2 center outputs (compact)
__device__ int   g_flag[NN];          // S1 membership flags
__device__ int   g_map[NN];           // node -> compact index
__device__ int   g_s1list[CAP];       // compact index -> node
__device__ int   g_ns1;               // |S1|

__device__ __forceinline__ void tf32_split(float x, uint32_t& hi, uint32_t& lo) {
    asm("cvt.rna.tf32.f32 %0, %1;" : "=r"(hi) : "f"(x));
    float r = x - __uint_as_float(hi);
    asm("cvt.rna.tf32.f32 %0, %1;" : "=r"(lo) : "f"(r));
}

// ---------------- detector + one-shot W split + deg/cnt/flag init (1 launch) ----------------
__global__ void k_detect(const int* __restrict__ a,
                         const float* __restrict__ w0, const float* __restrict__ w1,
                         const float* __restrict__ w2) {
    if (blockIdx.x == 0) {
        int i = threadIdx.x;                       // 512 threads
        int v  = a[i];
        int vp = (i > 0) ? a[i - 1] : 0;
        int ok = (v >= 0) && (v < GG) && (v >= vp);
        int all = __syncthreads_and(ok);
        if (i == 0) g_aIsBatch = all;
    } else if (blockIdx.x <= 96) {
        int idx = (blockIdx.x - 1) * 512 + threadIdx.x;   // 0..49151
        int layer = idx >> 14;
        int e = idx & 16383;
        int k = e >> 7, n = e & 127;
        const float* Wsel = (layer == 0) ? w0 : ((layer == 1) ? w1 : w2);
        uint32_t h, l;
        tf32_split(Wsel[k * 128 + n], h, l);
        int off = layer * 17408 + k * 136 + n;
        g_wfhi[off] = __uint_as_float(h);
        g_wflo[off] = __uint_as_float(l);
    } else {
        int i = (int)(blockIdx.x - 97) * 512 + threadIdx.x;
        if (i < NN) { g_deg[i] = 1.0f; g_cnt[i] = 0; g_flag[i] = 0; }
    }
}

__global__ void k_count(const int* __restrict__ ei, const float* __restrict__ w) {
    int e = blockIdx.x * blockDim.x + threadIdx.x;
    if (e < EE) {
        int c = ei[EE + e];
        atomicAdd(&g_deg[c], w[e]);
        atomicAdd(&g_cnt[c], 1);
    }
}

// ---------------- CSR build (scan1 also computes dinv in place) ----------------
__global__ void k_scan1() {   // blocks of 1024 over g_cnt
    __shared__ int s[1024];
    int tid = threadIdx.x;
    int i = blockIdx.x * 1024 + tid;
    if (i < NN) { float d = g_deg[i]; g_deg[i] = (d > 0.f) ? rsqrtf(d) : 0.f; }
    int v = (i < NN) ? g_cnt[i] : 0;
    s[tid] = v; __syncthreads();
    #pragma unroll
    for (int off = 1; off < 1024; off <<= 1) {
        int t = (tid >= off) ? s[tid - off] : 0;
        __syncthreads();
        s[tid] += t; __syncthreads();
    }
    if (i < NN) g_rowptr[i] = s[tid] - v;         // exclusive within block
    if (tid == 1023) g_part[blockIdx.x] = s[1023];
}

__global__ void k_scan2(int nblocks) {
    __shared__ int s[128];
    int tid = threadIdx.x;
    int v = (tid < nblocks) ? g_part[tid] : 0;
    s[tid] = v; __syncthreads();
    #pragma unroll
    for (int off = 1; off < 128; off <<= 1) {
        int t = (tid >= off) ? s[tid - off] : 0;
        __syncthreads();
        s[tid] += t; __syncthreads();
    }
    if (tid < nblocks) g_part[tid] = s[tid] - v;  // exclusive
    if (tid == 127) g_rowptr[NN] = s[127];
}

__global__ void k_scan3() {
    int i = blockIdx.x * blockDim.x + threadIdx.x;
    if (i < NN) { g_rowptr[i] += g_part[i >> 10]; g_cnt[i] = 0; }
}

// fused: CSR fill + norm computation + epack write (one edge pass)
__global__ void k_fill(const int* __restrict__ ei, const float* __restrict__ w) {
    int e = blockIdx.x * blockDim.x + threadIdx.x;
    if (e < EE) {
        int r = ei[e];
        int c = ei[EE + e];
        float nm = g_deg[r] * w[e] * g_deg[c];    // g_deg holds dinv
        int pos = g_rowptr[c] + atomicAdd(&g_cnt[c], 1);
        g_epack[pos] = make_int2(r, __float_as_int(nm));
    }
}

// ---------------- S1 set: mark centers + their in-neighbors ----------------
__global__ void k_mark(const int* __restrict__ cand_a, const int* __restrict__ cand_b) {
    const int* batch = g_aIsBatch ? cand_a : cand_b;
    int gtid = blockIdx.x * blockDim.x + threadIdx.x;
    int w = gtid >> 5, lane = gtid & 31;
    if (w >= 2 * GG) return;
    int gph = w >> 1, idx = w & 1;
    int c = 0;
    if (lane == 0) {
        int lo = 0, hi = NN;
        while (lo < hi) { int mid = (lo + hi) >> 1; if (batch[mid] < gph) lo = mid + 1; else hi = mid; }
        c = lo;
    }
    c = __shfl_sync(0xffffffffu, c, 0);
    int v = c + idx;
    if (lane == 0) g_flag[v] = 1;
    int p = g_rowptr[v], end = g_rowptr[v + 1];
    for (int t = p + lane; t < end; t += 32) g_flag[g_epack[t].x] = 1;
}

// ---------------- compact map scan over flags ----------------
__global__ void k_mscan1() {
    __shared__ int s[1024];
    int tid = threadIdx.x;
    int i = blockIdx.x * 1024 + tid;
    int v = (i < NN) ? g_flag[i] : 0;
    s[tid] = v; __syncthreads();
    #pragma unroll
    for (int off = 1; off < 1024; off <<= 1) {
        int t = (tid >= off) ? s[tid - off] : 0;
        __syncthreads();
        s[tid] += t; __syncthreads();
    }
    if (i < NN) g_map[i] = s[tid] - v;            // exclusive within block
    if (tid == 1023) g_part[blockIdx.x] = s[1023];
}

__global__ void k_mscan2(int nblocks) {
    __shared__ int s[128];
    int tid = threadIdx.x;
    int v = (tid < nblocks) ? g_part[tid] : 0;
    s[tid] = v; __syncthreads();
    #pragma unroll
    for (int off = 1; off < 128; off <<= 1) {
        int t = (tid >= off) ? s[tid - off] : 0;
        __syncthreads();
        s[tid] += t; __syncthreads();
    }
    if (tid < nblocks) g_part[tid] = s[tid] - v;
    if (tid == 127) g_ns1 = s[127];
}

__global__ void k_mscan3() {
    int i = blockIdx.x * blockDim.x + threadIdx.x;
    if (i < NN) {
        int m = g_map[i] + g_part[i >> 10];
        g_map[i] = m;
        if (g_flag[i] && m < CAP) g_s1list[m] = i;
    }
}

// ---------------- 3xTF32 tensor-core GEMM: Y[rows,128] = X[rows,128] @ W + opt bias/relu ----
// R9 config: BM=128, 512 threads, warp tile m16 x n64, K=128; pre-split W copy prologue.
#define MMA_TF32(acc, a0, a1, a2, a3, b0, b1)                               \
    asm volatile(                                                           \
        "mma.sync.aligned.m16n8k8.row.col.f32.tf32.tf32.f32 "               \
        "{%0,%1,%2,%3},{%4,%5,%6,%7},{%8,%9},{%0,%1,%2,%3};\n"              \
        : "+f"(acc[0]), "+f"(acc[1]), "+f"(acc[2]), "+f"(acc[3])            \
        : "r"(a0), "r"(a1), "r"(a2), "r"(a3), "r"(b0), "r"(b1))

__global__ void __launch_bounds__(512, 1)
k_gemm(const float* __restrict__ X, int layer, float* __restrict__ Y,
       const int* __restrict__ za, const int* __restrict__ zb,
       const float* __restrict__ ztab, int useEmbed, int rows,
       const int* __restrict__ rowsDev, const float* __restrict__ bias, int do_relu) {
    if (rowsDev) rows = *rowsDev;
    int row0 = blockIdx.x * 128;
    if (row0 >= rows) return;                     // uniform early-exit

    extern __shared__ float sm[];
    float* Xs  = sm;                      // [128][132]
    float* Whi = sm + 16896;              // [128][136]
    float* Wlo = Whi + 17408;
    int tid = threadIdx.x;

    {
        const float4* shi = (const float4*)(g_wfhi + layer * 17408);
        const float4* slo = (const float4*)(g_wflo + layer * 17408);
        float4* dhi = (float4*)Whi;
        float4* dlo = (float4*)Wlo;
        for (int idx = tid; idx < 4352; idx += 512) {
            dhi[idx] = shi[idx];
            dlo[idx] = slo[idx];
        }
    }
    const int* zsel = g_aIsBatch ? zb : za;
    #pragma unroll
    for (int i = 0; i < 8; ++i) {
        int idx = tid + i * 512;
        int m = idx >> 5, kv = idx & 31;
        int r = row0 + m;
        float4 v = make_float4(0.f, 0.f, 0.f, 0.f);
        if (r < rows) {
            const float4* src = useEmbed ? ((const float4*)ztab + (size_t)zsel[r] * 32)
                                         : ((const float4*)X + (size_t)r * 32);
            v = src[kv];
        }
        *(float4*)&Xs[m * 132 + kv * 4] = v;
    }
    __syncthreads();

    int wid = tid >> 5, lane = tid & 31;
    int m0 = (wid & 7) * 16;
    int n0 = (wid >> 3) * 64;
    int g  = lane >> 2;
    int q  = lane & 3;

    float acc[8][4];
    #pragma unroll
    for (int nt = 0; nt < 8; ++nt)
        #pragma unroll
        for (int j = 0; j < 4; ++j) acc[nt][j] = 0.f;

    #pragma unroll 2
    for (int ks = 0; ks < 16; ++ks) {
        int kb = ks * 8;
        uint32_t ah[4], al[4];
        int rb = m0 + g;
        tf32_split(Xs[rb * 132 + kb + q],           ah[0], al[0]);
        tf32_split(Xs[(rb + 8) * 132 + kb + q],     ah[1], al[1]);
        tf32_split(Xs[rb * 132 + kb + q + 4],       ah[2], al[2]);
        tf32_split(Xs[(rb + 8) * 132 + kb + q + 4], ah[3], al[3]);
        #pragma unroll
        for (int nt = 0; nt < 8; ++nt) {
            int nc = n0 + nt * 8 + g;
            uint32_t bh0 = __float_as_uint(Whi[(kb + q) * 136 + nc]);
            uint32_t bl0 = __float_as_uint(Wlo[(kb + q) * 136 + nc]);
            uint32_t bh1 = __float_as_uint(Whi[(kb + q + 4) * 136 + nc]);
            uint32_t bl1 = __float_as_uint(Wlo[(kb + q + 4) * 136 + nc]);
            MMA_TF32(acc[nt], ah[0], ah[1], ah[2], ah[3], bl0, bl1);
            MMA_TF32(acc[nt], al[0], al[1], al[2], al[3], bh0, bh1);
            MMA_TF32(acc[nt], ah[0], ah[1], ah[2], ah[3], bh0, bh1);
        }
    }

    {
        int r = row0 + m0 + g;
        #pragma unroll
        for (int nt = 0; nt < 8; ++nt) {
            int cc = n0 + nt * 8 + 2 * q;
            float2 bb = make_float2(0.f, 0.f);
            if (bias) bb = *(const float2*)&bias[cc];
            float o0 = acc[nt][0] + bb.x, o1 = acc[nt][1] + bb.y;
            float o2 = acc[nt][2] + bb.x, o3 = acc[nt][3] + bb.y;
            if (do_relu) {
                o0 = fmaxf(o0, 0.f); o1 = fmaxf(o1, 0.f);
                o2 = fmaxf(o2, 0.f); o3 = fmaxf(o3, 0.f);
            }
            if (r < rows)     *(float2*)&Y[r * 128 + cc]       = make_float2(o0, o1);
            if (r + 8 < rows) *(float2*)&Y[(r + 8) * 128 + cc] = make_float2(o2, o3);
        }
    }
}

// ---------------- full CSR gather-aggregate + bias (+ReLU) (layer 0) ----------------
__global__ void k_gather(const float* __restrict__ xw, const float* __restrict__ bias,
                         float* __restrict__ out, int do_relu) {
    int gtid = blockIdx.x * blockDim.x + threadIdx.x;
    int v = gtid >> 5;
    int lane = gtid & 31;
    if (v >= NN) return;

    const float4* xwv = (const float4*)xw;
    float di = g_deg[v];
    float s = di * di;
    float4 acc = xwv[(size_t)v * 32 + lane];
    acc.x *= s; acc.y *= s; acc.z *= s; acc.w *= s;

    int p = g_rowptr[v], end = g_rowptr[v + 1];
    if (p < end) {
        int2 pr = g_epack[p];
        for (++p; p < end; ++p) {
            int2 nxt = g_epack[p];
            float nm = __int_as_float(pr.y);
            float4 xv = xwv[(size_t)pr.x * 32 + lane];
            acc.x += nm * xv.x; acc.y += nm * xv.y;
            acc.z += nm * xv.z; acc.w += nm * xv.w;
            pr = nxt;
        }
        float nm = __int_as_float(pr.y);
        float4 xv = xwv[(size_t)pr.x * 32 + lane];
        acc.x += nm * xv.x; acc.y += nm * xv.y;
        acc.z += nm * xv.z; acc.w += nm * xv.w;
    }

    float4 b = ((const float4*)bias)[lane];
    acc.x += b.x; acc.y += b.y; acc.z += b.z; acc.w += b.w;
    if (do_relu) {
        acc.x = fmaxf(acc.x, 0.f); acc.y = fmaxf(acc.y, 0.f);
        acc.z = fmaxf(acc.z, 0.f); acc.w = fmaxf(acc.w, 0.f);
    }
    ((float4*)out)[(size_t)v * 32 + lane] = acc;
}

// ---------------- S1-only raw aggregate (layer-1 GEMM commuted out) ----------------
// compact row i aggregates x at node v = g_s1list[i]; no weights/bias.
__global__ void k_gather_s1(const float* __restrict__ x, float* __restrict__ outc) {
    int gtid = blockIdx.x * blockDim.x + threadIdx.x;
    int w = gtid >> 5;
    int lane = gtid & 31;
    if (w >= g_ns1) return;
    int v = g_s1list[w];

    const float4* xv4 = (const float4*)x;
    float di = g_deg[v];
    float s = di * di;
    float4 acc = xv4[(size_t)v * 32 + lane];
    acc.x *= s; acc.y *= s; acc.z *= s; acc.w *= s;

    int p = g_rowptr[v], end = g_rowptr[v + 1];
    if (p < end) {
        int2 pr = g_epack[p];
        for (++p; p < end; ++p) {
            int2 nxt = g_epack[p];
            float nm = __int_as_float(pr.y);
            float4 xv = xv4[(size_t)pr.x * 32 + lane];
            acc.x += nm * xv.x; acc.y += nm * xv.y;
            acc.z += nm * xv.z; acc.w += nm * xv.w;
            pr = nxt;
        }
        float nm = __int_as_float(pr.y);
        float4 xv = xv4[(size_t)pr.x * 32 + lane];
        acc.x += nm * xv.x; acc.y += nm * xv.y;
        acc.z += nm * xv.z; acc.w += nm * xv.w;
    }
    ((float4*)outc)[(size_t)w * 32 + lane] = acc;
}

// ---------------- layer-2 CENTER aggregate of compact x1 (via map) ----------------
__global__ void k_gather_ctr(const float* __restrict__ x1c,
                             const int* __restrict__ cand_a, const int* __restrict__ cand_b,
                             float* __restrict__ outc) {
    const int* batch = g_aIsBatch ? cand_a : cand_b;
    int gtid = blockIdx.x * blockDim.x + threadIdx.x;
    int w = gtid >> 5;
    int lane = gtid & 31;
    if (w >= 2 * GG) return;
    int gph = w >> 1, idx = w & 1;

    int c = 0;
    if (lane == 0) {
        int lo = 0, hi = NN;
        while (lo < hi) { int mid = (lo + hi) >> 1; if (batch[mid] < gph) lo = mid + 1; else hi = mid; }
        c = lo;
    }
    c = __shfl_sync(0xffffffffu, c, 0);
    int v = c + idx;

    const float4* xv4 = (const float4*)x1c;
    float di = g_deg[v];
    float s = di * di;
    float4 acc = xv4[(size_t)g_map[v] * 32 + lane];
    acc.x *= s; acc.y *= s; acc.z *= s; acc.w *= s;

    int p = g_rowptr[v], end = g_rowptr[v + 1];
    for (; p < end; ++p) {
        int2 e = g_epack[p];
        float nm = __int_as_float(e.y);
        float4 xv = xv4[(size_t)g_map[e.x] * 32 + lane];
        acc.x += nm * xv.x; acc.y += nm * xv.y;
        acc.z += nm * xv.z; acc.w += nm * xv.w;
    }
    ((float4*)outc)[w * 32 + lane] = acc;
}

// ---------------- readout (reads compact center buffer) ----------------
__global__ void k_readout(const float* __restrict__ C,
                          const float* __restrict__ W1, const float* __restrict__ b1,
                          const float* __restrict__ W2, const float* __restrict__ b2,
                          float* __restrict__ out) {
    __shared__ float h[128];
    __shared__ float red[4];
    int g = blockIdx.x, j = threadIdx.x;
    h[j] = C[(2 * g) * 128 + j] * C[(2 * g + 1) * 128 + j];
    __syncthreads();
    float acc = b1[j];
    #pragma unroll 8
    for (int k = 0; k < 128; ++k) acc += h[k] * W1[k * 128 + j];
    acc = fmaxf(acc, 0.f);
    float v = acc * W2[j];
    #pragma unroll
    for (int o = 16; o; o >>= 1) v += __shfl_xor_sync(0xffffffffu, v, o);
    if ((j & 31) == 0) red[j >> 5] = v;
    __syncthreads();
    if (j == 0) out[g] = red[0] + red[1] + red[2] + red[3] + b2[0];
}

// ---------------- launch: bind inputs BY SIZE (metadata order is unknown) ----------------
extern "C" void kernel_launch(void* const* d_in, const int* in_sizes, int n_in,
                              void* d_out, int out_size) {
    const int* i100k[2] = {0, 0}; int n100k = 0;
    const void* v16k[4] = {0, 0, 0, 0}; int n16k = 0;
    const void* v128[8] = {0, 0, 0, 0, 0, 0, 0, 0}; int n128 = 0;
    const int*   ei = 0; const float* ew = 0; const float* ztab = 0;
    const float* packedW = 0; const float* packedB = 0; const float* lin2b = 0;

    for (int i = 0; i < n_in; ++i) {
        int s = in_sizes[i];
        if      (s == 2 * EE)      ei   = (const int*)d_in[i];
        else if (s == EE)          ew   = (const float*)d_in[i];
        else if (s == 1000 * HH)   ztab = (const float*)d_in[i];
        else if (s == NN)          { if (n100k < 2) i100k[n100k++] = (const int*)d_in[i]; }
        else if (s == HH * HH)     { if (n16k < 4) v16k[n16k++] = d_in[i]; }
        else if (s == 3 * HH * HH) packedW = (const float*)d_in[i];
        else if (s == HH)          { if (n128 < 8) v128[n128++] = d_in[i]; }
        else if (s == 3 * HH)      packedB = (const float*)d_in[i];
        else if (s == 1)           lin2b = (const float*)d_in[i];
    }

    const float* convW[3]; const float* convB[3];
    const float* lin1W; const float* lin1b; const float* lin2W;
    if (packedW) {
        convW[0] = packedW; convW[1] = packedW + HH * HH; convW[2] = packedW + 2 * HH * HH;
        lin1W = (const float*)v16k[0];
    } else {
        convW[0] = (const float*)v16k[0]; convW[1] = (const float*)v16k[1];
        convW[2] = (const float*)v16k[2]; lin1W = (const float*)v16k[3];
    }
    if (packedB) {
        convB[0] = packedB; convB[1] = packedB + HH; convB[2] = packedB + 2 * HH;
        lin1b = (const float*)v128[0]; lin2W = (const float*)v128[1];
    } else {
        convB[0] = (const float*)v128[0]; convB[1] = (const float*)v128[1];
        convB[2] = (const float*)v128[2];
        lin1b = (const float*)v128[3]; lin2W = (const float*)v128[4];
    }
    float* out = (float*)d_out;

    float *A, *B, *CA, *C;
    int *ns1p;
    cudaGetSymbolAddress((void**)&A, g_bufA);
    cudaGetSymbolAddress((void**)&B, g_bufB);
    cudaGetSymbolAddress((void**)&CA, g_ctragg);
    cudaGetSymbolAddress((void**)&C, g_ctr);
    cudaGetSymbolAddress((void**)&ns1p, g_ns1);
    float* A1AGG = B;                  // compact S1 aggregates  [CAP x 128]
    float* X1C   = B + (size_t)CAP * HH;  // compact x1           [CAP x 128]

    const int SMEM = (16896 + 2 * 17408) * 4;  // 206848
    cudaFuncSetAttribute(k_gemm, cudaFuncAttributeMaxDynamicSharedMemorySize, SMEM);

    const int TB = 256;
    int nblk_n  = (NN + TB - 1) / TB;         // 391
    int nblk_e  = (EE + TB - 1) / TB;         // 6250
    int nblk_nh = (NN * 32 + TB - 1) / TB;    // 12500
    int scan_blocks = (NN + 1023) / 1024;     // 98
    int gemm_blocks = (NN + 127) / 128;       // 782

    // launch 0: detect + W split + deg/cnt/flag init (fused)
    k_detect<<<97 + 196, 512>>>(i100k[0], convW[0], convW[1], convW[2]);
    // launch 1,2
    k_count<<<nblk_e, TB>>>(ei, ew);
    k_scan1<<<scan_blocks, 1024>>>();         // also computes dinv

    // launch 3: layer-0 GEMM (embedding fused) — profiler capture slot
    k_gemm<<<gemm_blocks, 512, SMEM>>>(A, 0, B, i100k[0], i100k[1], ztab, 1, NN, 0, 0, 0);

    // CSR build (rest)
    k_scan2<<<1, 128>>>(scan_blocks);
    k_scan3<<<nblk_n, TB>>>();
    k_fill <<<nblk_e, TB>>>(ei, ew);

    // layer 0 aggregate (full, relu): A = x0
    k_gather<<<nblk_nh, TB>>>(B, convB[0], A, 1);

    // S1 set construction (centers + in-neighbors), compact map/list
    k_mark  <<<(2 * GG * 32 + TB - 1) / TB, TB>>>(i100k[0], i100k[1]);
    k_mscan1<<<scan_blocks, 1024>>>();
    k_mscan2<<<1, 128>>>(scan_blocks);
    k_mscan3<<<nblk_n, TB>>>();

    // layer 1 (commuted): raw aggregate of x0 at S1, then compact GEMM + bias + relu
    k_gather_s1<<<(CAP * 32 + TB - 1) / TB, TB>>>(A, A1AGG);
    k_gemm<<<(CAP + 127) / 128, 512, SMEM>>>(A1AGG, 1, X1C, i100k[0], i100k[1], ztab, 0,
                                             CAP, ns1p, convB[1], 1);

    // layer 2 (commuted): center aggregate of compact x1, then 1000-row GEMM + bias
    k_gather_ctr<<<(2 * GG * 32 + TB - 1) / TB, TB>>>(X1C, i100k[0], i100k[1], CA);
    k_gemm<<<(2 * GG + 127) / 128, 512, SMEM>>>(CA, 2, C, i100k[0], i100k[1], ztab, 0,
                                                2 * GG, 0, convB[2], 0);

    // readout
    k_readout<<<GG, 128>>>(C, lin1W, lin1b, lin2W, lin2b, out);
}